// round 13
// baseline (speedup 1.0000x reference)
#include <cuda_runtime.h>
#include <cuda_fp16.h>
#include <cstdint>

#define N_NODES 8192
#define D_IN    512
#define D_OUT   256
#define KC      64
#define NCHL    64            // chunks per CTA (half of K)
#define MT      64
#define FTH     512

// ---------------- scratch (device globals) ----------------------------------
static __device__ float    g_wh [N_NODES * D_OUT];     // fp32 wh (8 MB)
static __device__ __half   g_whT[D_OUT * N_NODES];     // fp16 wh^T (4 MB)
static __device__ float    g_pacc[2 * N_NODES * D_OUT];// partial acc (16 MB)
static __device__ float    g_plsum[2 * N_NODES];
static __device__ float    g_ssrc[N_NODES];
static __device__ float    g_t[N_NODES];
static __device__ uint32_t g_EF[N_NODES];              // half2 {E, F} (32 KB, hot)
static __device__ float    g_alpha[N_NODES];
static __device__ float    g_beta[N_NODES];
static __device__ float    g_thr[N_NODES];
static __device__ unsigned g_Tbits;

// ---------------- PTX helpers -----------------------------------------------
__device__ __forceinline__ uint32_t smem_u32(const void* p) {
    uint32_t a;
    asm("{ .reg .u64 t; cvta.to.shared.u64 t, %1; cvt.u32.u64 %0, t; }"
        : "=r"(a) : "l"(p));
    return a;
}
__device__ __forceinline__ void ldmatrix_x4(uint32_t& r0, uint32_t& r1,
                                            uint32_t& r2, uint32_t& r3,
                                            uint32_t addr) {
    asm volatile("ldmatrix.sync.aligned.m8n8.x4.shared.b16 {%0,%1,%2,%3}, [%4];"
                 : "=r"(r0), "=r"(r1), "=r"(r2), "=r"(r3) : "r"(addr));
}
__device__ __forceinline__ void mma16816(float* c,
                                         uint32_t a0, uint32_t a1, uint32_t a2, uint32_t a3,
                                         uint32_t b0, uint32_t b1) {
    asm volatile("mma.sync.aligned.m16n8k16.row.col.f32.f16.f16.f32 "
                 "{%0,%1,%2,%3}, {%4,%5,%6,%7}, {%8,%9}, {%0,%1,%2,%3};"
                 : "+f"(c[0]), "+f"(c[1]), "+f"(c[2]), "+f"(c[3])
                 : "r"(a0), "r"(a1), "r"(a2), "r"(a3), "r"(b0), "r"(b1));
}
__device__ __forceinline__ void cp16(uint32_t dst, const void* src) {
    asm volatile("cp.async.ca.shared.global [%0], [%1], 16;"
                 :: "r"(dst), "l"(src) : "memory");
}
#define CP_COMMIT() asm volatile("cp.async.commit_group;" ::: "memory")
#define CP_WAIT0()  asm volatile("cp.async.wait_group 0;" ::: "memory")

__device__ __forceinline__ unsigned fkey(float x) {
    int i = __float_as_int(x);
    return i >= 0 ? ((unsigned)i | 0x80000000u) : ~(unsigned)i;
}
__device__ __forceinline__ float finv(unsigned k) {
    return (k & 0x80000000u) ? __int_as_float((int)(k & 0x7fffffffu))
                             : __int_as_float((int)~k);
}
__device__ __forceinline__ uint32_t packh2(float a, float b) {
    __half2 h = __floats2half2_rn(a, b);
    return *(uint32_t*)&h;
}
__device__ __forceinline__ float2 unph2(uint32_t u) {
    return __half22float2(*(__half2*)&u);
}

// ==================== Kernel 1: wh = h @ W^T + b  (HMMA fp16) ===============
#define GLD 72
static constexpr uint32_t GA_BUF = 128 * GLD * 2;
static constexpr uint32_t GB_OFF = 2 * GA_BUF;
static constexpr uint32_t GEMM_SMEM = 4 * GA_BUF;
#define LDT 136

__global__ void __launch_bounds__(512) gemm_wh_kernel(
    const float* __restrict__ h, const float* __restrict__ W,
    const float* __restrict__ Wb)
{
    extern __shared__ __align__(16) char smem[];
    const uint32_t sbase = smem_u32(smem);
    const int tid  = threadIdx.x;
    const int lane = tid & 31;
    const int warp = tid >> 5;
    const int mw = warp >> 2;
    const int nw = warp & 3;
    const int row0 = blockIdx.y * 128;
    const int col0 = blockIdx.x * 128;

    if (blockIdx.x == 0 && blockIdx.y == 0 && tid == 0) g_Tbits = 0u;

    auto stage = [&](int kb, int buf) {
        __half* Ah = (__half*)(smem + buf * GA_BUF);
        __half* Bh = (__half*)(smem + GB_OFF + buf * GA_BUF);
        #pragma unroll
        for (int i = 0; i < 4; i++) {
            int f = tid + i * 512;
            int r = f >> 4;
            int c4 = (f & 15) << 2;
            float4 v = *(const float4*)&h[(size_t)(row0 + r) * D_IN + kb + c4];
            *(uint2*)(Ah + r * GLD + c4) = make_uint2(packh2(v.x, v.y), packh2(v.z, v.w));
            float4 u = *(const float4*)&W[(size_t)(col0 + r) * D_IN + kb + c4];
            *(uint2*)(Bh + r * GLD + c4) = make_uint2(packh2(u.x, u.y), packh2(u.z, u.w));
        }
    };

    const uint32_t a_lane0 = sbase +
        (uint32_t)(((mw * 32 + (lane & 15)) * GLD + (lane >> 4) * 8) * 2);
    const uint32_t b_lane0 = sbase + GB_OFF +
        (uint32_t)(((nw * 32 + (lane & 7) + ((lane >> 4) << 3)) * GLD
                    + ((lane >> 3) & 1) * 8) * 2);

    float acc[2][4][4];
    #pragma unroll
    for (int mi = 0; mi < 2; mi++)
        #pragma unroll
        for (int nt = 0; nt < 4; nt++)
            #pragma unroll
            for (int u = 0; u < 4; u++) acc[mi][nt][u] = 0.f;

    stage(0, 0);
    __syncthreads();

    #pragma unroll 1
    for (int kt = 0; kt < 8; kt++) {
        const int buf = kt & 1;
        if (kt < 7) stage((kt + 1) * 64, buf ^ 1);
        const uint32_t a_lane = a_lane0 + (uint32_t)buf * GA_BUF;
        const uint32_t b_lane = b_lane0 + (uint32_t)buf * GA_BUF;
        #pragma unroll
        for (int ks = 0; ks < 4; ks++) {
            uint32_t b[2][4];
            ldmatrix_x4(b[0][0], b[0][1], b[0][2], b[0][3], b_lane + ks * 32);
            ldmatrix_x4(b[1][0], b[1][1], b[1][2], b[1][3],
                        b_lane + 16 * GLD * 2 + ks * 32);
            #pragma unroll
            for (int mi = 0; mi < 2; mi++) {
                uint32_t a0, a1, a2, a3;
                ldmatrix_x4(a0, a1, a2, a3, a_lane + mi * 16 * GLD * 2 + ks * 32);
                mma16816(acc[mi][0], a0, a1, a2, a3, b[0][0], b[0][1]);
                mma16816(acc[mi][1], a0, a1, a2, a3, b[0][2], b[0][3]);
                mma16816(acc[mi][2], a0, a1, a2, a3, b[1][0], b[1][1]);
                mma16816(acc[mi][3], a0, a1, a2, a3, b[1][2], b[1][3]);
            }
        }
        __syncthreads();
    }

    __half* tT = (__half*)smem;
    #pragma unroll
    for (int nt = 0; nt < 4; nt++) {
        int cl = nw * 32 + nt * 8 + ((lane & 3) << 1);
        float2 bb = *(const float2*)&Wb[col0 + cl];
        #pragma unroll
        for (int mi = 0; mi < 2; mi++) {
            int rl0 = mw * 32 + mi * 16 + (lane >> 2);
            int rl1 = rl0 + 8;
            float v00 = acc[mi][nt][0] + bb.x;
            float v01 = acc[mi][nt][1] + bb.y;
            float v10 = acc[mi][nt][2] + bb.x;
            float v11 = acc[mi][nt][3] + bb.y;
            *(float2*)&g_wh[(size_t)(row0 + rl0) * D_OUT + col0 + cl] = make_float2(v00, v01);
            *(float2*)&g_wh[(size_t)(row0 + rl1) * D_OUT + col0 + cl] = make_float2(v10, v11);
            tT[cl * LDT + rl0]       = __float2half(v00);
            tT[(cl + 1) * LDT + rl0] = __float2half(v01);
            tT[cl * LDT + rl1]       = __float2half(v10);
            tT[(cl + 1) * LDT + rl1] = __float2half(v11);
        }
    }
    __syncthreads();
    {
        int c = tid >> 2;
        int seg = (tid & 3) << 5;
        const uint4* src = (const uint4*)(tT + c * LDT + seg);
        uint4* dst = (uint4*)(g_whT + (size_t)(col0 + c) * N_NODES + row0 + seg);
        #pragma unroll
        for (int i = 0; i < 4; i++) dst[i] = src[i];
    }
}

// ==================== Kernel 2: per-row scores (+ global max of t) ==========
__global__ void __launch_bounds__(256) scores_kernel(const float* __restrict__ aw)
{
    const int lane = threadIdx.x & 31;
    const int warp = threadIdx.x >> 5;
    const int row  = blockIdx.x * 8 + warp;

    const float4* whr = (const float4*)&g_wh[(size_t)row * D_OUT];
    float4 w0 = whr[lane * 2];
    float4 w1 = whr[lane * 2 + 1];
    const float4* as = (const float4*)aw;
    const float4* ad = (const float4*)(aw + D_OUT);
    float4 a0 = as[lane * 2], a1 = as[lane * 2 + 1];
    float4 b0 = ad[lane * 2], b1 = ad[lane * 2 + 1];

    float ss = w0.x*a0.x + w0.y*a0.y + w0.z*a0.z + w0.w*a0.w
             + w1.x*a1.x + w1.y*a1.y + w1.z*a1.z + w1.w*a1.w;
    float sd = w0.x*b0.x + w0.y*b0.y + w0.z*b0.z + w0.w*b0.w
             + w1.x*b1.x + w1.y*b1.y + w1.z*b1.z + w1.w*b1.w;
    #pragma unroll
    for (int o = 16; o; o >>= 1) {
        ss += __shfl_xor_sync(0xffffffffu, ss, o);
        sd += __shfl_xor_sync(0xffffffffu, sd, o);
    }
    if (lane == 0) {
        g_ssrc[row] = ss;
        g_t[row]    = sd;
        atomicMax(&g_Tbits, fkey(sd));
    }
}

// ==================== Kernel 2b: elementwise finalize ========================
__global__ void __launch_bounds__(512) finalize_kernel(const float* __restrict__ abp)
{
    const int i = blockIdx.x * 512 + threadIdx.x;
    const float T = finv(g_Tbits);
    const float ab = abp[0];
    float t = g_t[i];
    g_EF[i] = packh2(__expf(t - T), __expf(0.2f * (t - T)));
    float u = g_ssrc[i] + ab + T;
    float M = u > 0.f ? u : 0.2f * u;
    g_alpha[i] = __expf(u - M);
    g_beta[i]  = __expf(0.2f * u - M);
    g_thr[i]   = __expf(-u);
}

// ==================== Kernel 3: HMMA flash (R8 core, K-split 2, occ=2) ======
#define LD 72
static constexpr uint32_t BS_BUF = 256 * LD * 2;          // 36864
static constexpr uint32_t AS_OFF = 2 * BS_BUF;            // 73728
static constexpr uint32_t AS_BUF = MT * LD * 2;           // 9216
static constexpr uint32_t LS_OFF = AS_OFF + 2 * AS_BUF;   // 92160
static constexpr uint32_t SMEM_TOTAL = LS_OFF + 256;      // 92416  (2 CTAs/SM)

__global__ void __launch_bounds__(FTH, 2) flash_mma_kernel(const int* __restrict__ adj)
{
    extern __shared__ __align__(16) char smem[];
    const uint32_t sbase = smem_u32(smem);
    float* lsum_s = (float*)(smem + LS_OFF);

    const int tid  = threadIdx.x;
    const int lane = tid & 31;
    const int warp = tid >> 5;
    const int rb = blockIdx.x >> 1;
    const int kh = blockIdx.x & 1;
    const int rowbase = rb * MT;
    const int kbase = kh * (N_NODES / 2);

    // ---- per-thread P-gen constants ----
    const int prow = tid >> 3;           // 0..63
    const int pseg = tid & 7;            // 8 j's each
    const int row  = rowbase + prow;
    const float alpha = g_alpha[row];
    const float beta  = g_beta[row];
    const float thr   = g_thr[row];
    float lpriv = 0.f;

    const int* adjrow = adj + (size_t)row * N_NODES + kbase;
    const uint32_t a_st0 = sbase + AS_OFF + (uint32_t)((prow * LD + pseg * 8) * 2);

    // ---- mma addressing: warp grid 2m x 8n ----
    const int mw = warp >> 3;
    const int nw = warp & 7;
    const uint32_t a_lane0 = sbase + AS_OFF +
        (uint32_t)(((mw * 32 + (lane & 15)) * LD + (lane >> 4) * 8) * 2);
    const uint32_t b_lane0 = sbase +
        (uint32_t)(((nw * 32 + (lane & 7) + ((lane >> 4) << 3)) * LD
                    + ((lane >> 3) & 1) * 8) * 2);

    float acc[2][4][4];
    #pragma unroll
    for (int mi = 0; mi < 2; mi++)
        #pragma unroll
        for (int nt = 0; nt < 4; nt++)
            #pragma unroll
            for (int u = 0; u < 4; u++) acc[mi][nt][u] = 0.f;

    // ---- B stage via cp.async: 4 x 16B per thread ----
    auto stageB = [&](int kcL, int buf) {
        const int k0 = kbase + kcL * KC;
        const uint32_t bb = sbase + (uint32_t)buf * BS_BUF;
        #pragma unroll
        for (int i = 0; i < 4; i++) {
            int f = tid + i * FTH;
            int n = f >> 3;
            int c = (f & 7) * 8;
            cp16(bb + (uint32_t)((n * LD + c) * 2),
                 g_whT + (size_t)n * N_NODES + k0 + c);
        }
    };

    // ---- P-gen: adj from regs, EF via __ldg (hot 32 KB table) ----
    auto pgen = [&](int kcL, int buf, int4 q0, int4 q1) {
        const int jb = kbase + kcL * KC + pseg * 8;
        const uint4* ep = (const uint4*)(g_EF + jb);
        uint4 u0 = __ldg(ep);
        uint4 u1 = __ldg(ep + 1);
        float2 ef;
        ef = unph2(u0.x); float p0 = q0.x > 0 ? (ef.x > thr ? alpha * ef.x : beta * ef.y) : 0.f;
        ef = unph2(u0.y); float p1 = q0.y > 0 ? (ef.x > thr ? alpha * ef.x : beta * ef.y) : 0.f;
        ef = unph2(u0.z); float p2 = q0.z > 0 ? (ef.x > thr ? alpha * ef.x : beta * ef.y) : 0.f;
        ef = unph2(u0.w); float p3 = q0.w > 0 ? (ef.x > thr ? alpha * ef.x : beta * ef.y) : 0.f;
        ef = unph2(u1.x); float p4 = q1.x > 0 ? (ef.x > thr ? alpha * ef.x : beta * ef.y) : 0.f;
        ef = unph2(u1.y); float p5 = q1.y > 0 ? (ef.x > thr ? alpha * ef.x : beta * ef.y) : 0.f;
        ef = unph2(u1.z); float p6 = q1.z > 0 ? (ef.x > thr ? alpha * ef.x : beta * ef.y) : 0.f;
        ef = unph2(u1.w); float p7 = q1.w > 0 ? (ef.x > thr ? alpha * ef.x : beta * ef.y) : 0.f;
        lpriv += ((p0 + p1) + (p2 + p3)) + ((p4 + p5) + (p6 + p7));
        uint4 w;
        w.x = packh2(p0, p1); w.y = packh2(p2, p3);
        w.z = packh2(p4, p5); w.w = packh2(p6, p7);
        uint32_t dst = a_st0 + (uint32_t)buf * AS_BUF;
        asm volatile("st.shared.v4.b32 [%0], {%1,%2,%3,%4};"
                     :: "r"(dst), "r"(w.x), "r"(w.y), "r"(w.z), "r"(w.w) : "memory");
    };

    // ---- prologue ----
    stageB(0, 0);
    CP_COMMIT();
    {
        const int4* ap = (const int4*)(adjrow) + pseg * 2;
        int4 q0 = ap[0], q1 = ap[1];
        pgen(0, 0, q0, q1);
    }
    CP_WAIT0();
    __syncthreads();          // Bs[0], As[0] ready

    // ---- main loop: one sync per chunk ----
    #pragma unroll 2
    for (int kcL = 0; kcL < NCHL; kcL++) {
        const int buf = kcL & 1;
        int4 qn0, qn1;
        if (kcL + 1 < NCHL) {
            stageB(kcL + 1, buf ^ 1);
            CP_COMMIT();
            const int4* ap = (const int4*)(adjrow + (kcL + 1) * KC) + pseg * 2;
            qn0 = ap[0]; qn1 = ap[1];
        }

        const uint32_t a_lane = a_lane0 + (uint32_t)buf * AS_BUF;
        const uint32_t b_lane = b_lane0 + (uint32_t)buf * BS_BUF;
        #pragma unroll
        for (int ks = 0; ks < 4; ks++) {
            uint32_t b0[4], b1[4];
            ldmatrix_x4(b0[0], b0[1], b0[2], b0[3],
                        b_lane + (uint32_t)(ks * 32));
            ldmatrix_x4(b1[0], b1[1], b1[2], b1[3],
                        b_lane + (uint32_t)(16 * LD * 2 + ks * 32));
            #pragma unroll
            for (int mi = 0; mi < 2; mi++) {
                uint32_t a0, a1, a2, a3;
                ldmatrix_x4(a0, a1, a2, a3,
                            a_lane + (uint32_t)(mi * 16 * LD * 2 + ks * 32));
                mma16816(acc[mi][0], a0, a1, a2, a3, b0[0], b0[1]);
                mma16816(acc[mi][1], a0, a1, a2, a3, b0[2], b0[3]);
                mma16816(acc[mi][2], a0, a1, a2, a3, b1[0], b1[1]);
                mma16816(acc[mi][3], a0, a1, a2, a3, b1[2], b1[3]);
            }
        }
        if (kcL + 1 < NCHL) pgen(kcL + 1, buf ^ 1, qn0, qn1);
        CP_WAIT0();
        __syncthreads();
    }

    // ---- lsum partial ----
    lpriv += __shfl_xor_sync(0xffffffffu, lpriv, 1);
    lpriv += __shfl_xor_sync(0xffffffffu, lpriv, 2);
    lpriv += __shfl_xor_sync(0xffffffffu, lpriv, 4);
    if ((lane & 7) == 0) lsum_s[prow] = lpriv;
    __syncthreads();
    if (tid < MT) g_plsum[kh * N_NODES + rowbase + tid] = lsum_s[tid];

    // ---- write raw partial acc ----
    float* pout = g_pacc + (size_t)kh * N_NODES * D_OUT;
    #pragma unroll
    for (int mi = 0; mi < 2; mi++) {
        int r0 = mw * 32 + mi * 16 + (lane >> 2);
        int r1 = r0 + 8;
        #pragma unroll
        for (int nt = 0; nt < 4; nt++) {
            int c = nw * 32 + nt * 8 + ((lane & 3) << 1);
            *(float2*)&pout[(size_t)(rowbase + r0) * D_OUT + c] =
                make_float2(acc[mi][nt][0], acc[mi][nt][1]);
            *(float2*)&pout[(size_t)(rowbase + r1) * D_OUT + c] =
                make_float2(acc[mi][nt][2], acc[mi][nt][3]);
        }
    }
}

// ==================== Kernel 4: combine partials ============================
__global__ void __launch_bounds__(512) reduce_kernel(float* __restrict__ out)
{
    const int idx = blockIdx.x * 512 + threadIdx.x;   // float4 index
    const int row = idx >> 6;
    const float inv = 1.f / (g_plsum[row] + g_plsum[N_NODES + row]);
    float4 a = ((const float4*)g_pacc)[idx];
    float4 b = ((const float4*)g_pacc)[N_NODES * D_OUT / 4 + idx];
    float4 o;
    o.x = (a.x + b.x) * inv;
    o.y = (a.y + b.y) * inv;
    o.z = (a.z + b.z) * inv;
    o.w = (a.w + b.w) * inv;
    ((float4*)out)[idx] = o;
}

// ==================== launch ================================================
extern "C" void kernel_launch(void* const* d_in, const int* in_sizes, int n_in,
                              void* d_out, int out_size)
{
    const float* h   = (const float*)d_in[0];
    const int*   adj = (const int*)  d_in[1];
    const float* Ww  = (const float*)d_in[2];
    const float* Wb  = (const float*)d_in[3];
    const float* aw  = (const float*)d_in[4];
    const float* ab  = (const float*)d_in[5];
    float* out = (float*)d_out;

    cudaFuncSetAttribute(gemm_wh_kernel,
                         cudaFuncAttributeMaxDynamicSharedMemorySize, GEMM_SMEM);
    cudaFuncSetAttribute(flash_mma_kernel,
                         cudaFuncAttributeMaxDynamicSharedMemorySize, SMEM_TOTAL);

    gemm_wh_kernel<<<dim3(D_OUT / 128, N_NODES / 128), 512, GEMM_SMEM>>>(h, Ww, Wb);
    scores_kernel<<<N_NODES / 8, 256>>>(aw);
    finalize_kernel<<<N_NODES / 512, 512>>>(ab);
    flash_mma_kernel<<<(N_NODES / MT) * 2, FTH, SMEM_TOTAL>>>(adj);
    reduce_kernel<<<N_NODES * D_OUT / 4 / 512, 512>>>(out);
}

// round 14
// speedup vs baseline: 1.0861x; 1.0861x over previous
#include <cuda_runtime.h>
#include <cuda_fp16.h>
#include <cstdint>

#define N_NODES 8192
#define D_IN    512
#define D_OUT   256
#define KC      64
#define NCHL    64            // chunks per CTA (half of K)
#define MT      64
#define FTH     256

// ---------------- scratch (device globals) ----------------------------------
static __device__ float    g_wh [N_NODES * D_OUT];     // fp32 wh (8 MB)
static __device__ __half   g_whT[D_OUT * N_NODES];     // fp16 wh^T (4 MB)
static __device__ float    g_pacc[2 * N_NODES * D_OUT];// partial acc (16 MB)
static __device__ float    g_plsum[2 * N_NODES];
static __device__ float    g_ssrc[N_NODES];
static __device__ float    g_t[N_NODES];
static __device__ uint32_t g_EF[N_NODES];              // half2 {E, F} (32 KB, hot)
static __device__ float    g_alpha[N_NODES];
static __device__ float    g_beta[N_NODES];
static __device__ float    g_thr[N_NODES];
static __device__ unsigned g_Tbits;

// ---------------- PTX helpers -----------------------------------------------
__device__ __forceinline__ uint32_t smem_u32(const void* p) {
    uint32_t a;
    asm("{ .reg .u64 t; cvta.to.shared.u64 t, %1; cvt.u32.u64 %0, t; }"
        : "=r"(a) : "l"(p));
    return a;
}
__device__ __forceinline__ void ldmatrix_x4(uint32_t& r0, uint32_t& r1,
                                            uint32_t& r2, uint32_t& r3,
                                            uint32_t addr) {
    asm volatile("ldmatrix.sync.aligned.m8n8.x4.shared.b16 {%0,%1,%2,%3}, [%4];"
                 : "=r"(r0), "=r"(r1), "=r"(r2), "=r"(r3) : "r"(addr));
}
__device__ __forceinline__ void mma16816(float* c,
                                         uint32_t a0, uint32_t a1, uint32_t a2, uint32_t a3,
                                         uint32_t b0, uint32_t b1) {
    asm volatile("mma.sync.aligned.m16n8k16.row.col.f32.f16.f16.f32 "
                 "{%0,%1,%2,%3}, {%4,%5,%6,%7}, {%8,%9}, {%0,%1,%2,%3};"
                 : "+f"(c[0]), "+f"(c[1]), "+f"(c[2]), "+f"(c[3])
                 : "r"(a0), "r"(a1), "r"(a2), "r"(a3), "r"(b0), "r"(b1));
}
__device__ __forceinline__ void cp16(uint32_t dst, const void* src) {
    asm volatile("cp.async.ca.shared.global [%0], [%1], 16;"
                 :: "r"(dst), "l"(src) : "memory");
}
#define CP_COMMIT() asm volatile("cp.async.commit_group;" ::: "memory")
#define CP_WAIT0()  asm volatile("cp.async.wait_group 0;" ::: "memory")

__device__ __forceinline__ unsigned fkey(float x) {
    int i = __float_as_int(x);
    return i >= 0 ? ((unsigned)i | 0x80000000u) : ~(unsigned)i;
}
__device__ __forceinline__ float finv(unsigned k) {
    return (k & 0x80000000u) ? __int_as_float((int)(k & 0x7fffffffu))
                             : __int_as_float((int)~k);
}
__device__ __forceinline__ uint32_t packh2(float a, float b) {
    __half2 h = __floats2half2_rn(a, b);
    return *(uint32_t*)&h;
}
__device__ __forceinline__ float2 unph2(uint32_t u) {
    return __half22float2(*(__half2*)&u);
}

// ==================== Kernel 1: wh = h @ W^T + b  (HMMA fp16) ===============
#define GLD 72
static constexpr uint32_t GA_BUF = 128 * GLD * 2;
static constexpr uint32_t GB_OFF = 2 * GA_BUF;
static constexpr uint32_t GEMM_SMEM = 4 * GA_BUF;
#define LDT 136

__global__ void __launch_bounds__(512) gemm_wh_kernel(
    const float* __restrict__ h, const float* __restrict__ W,
    const float* __restrict__ Wb)
{
    extern __shared__ __align__(16) char smem[];
    const uint32_t sbase = smem_u32(smem);
    const int tid  = threadIdx.x;
    const int lane = tid & 31;
    const int warp = tid >> 5;
    const int mw = warp >> 2;
    const int nw = warp & 3;
    const int row0 = blockIdx.y * 128;
    const int col0 = blockIdx.x * 128;

    if (blockIdx.x == 0 && blockIdx.y == 0 && tid == 0) g_Tbits = 0u;

    auto stage = [&](int kb, int buf) {
        __half* Ah = (__half*)(smem + buf * GA_BUF);
        __half* Bh = (__half*)(smem + GB_OFF + buf * GA_BUF);
        #pragma unroll
        for (int i = 0; i < 4; i++) {
            int f = tid + i * 512;
            int r = f >> 4;
            int c4 = (f & 15) << 2;
            float4 v = *(const float4*)&h[(size_t)(row0 + r) * D_IN + kb + c4];
            *(uint2*)(Ah + r * GLD + c4) = make_uint2(packh2(v.x, v.y), packh2(v.z, v.w));
            float4 u = *(const float4*)&W[(size_t)(col0 + r) * D_IN + kb + c4];
            *(uint2*)(Bh + r * GLD + c4) = make_uint2(packh2(u.x, u.y), packh2(u.z, u.w));
        }
    };

    const uint32_t a_lane0 = sbase +
        (uint32_t)(((mw * 32 + (lane & 15)) * GLD + (lane >> 4) * 8) * 2);
    const uint32_t b_lane0 = sbase + GB_OFF +
        (uint32_t)(((nw * 32 + (lane & 7) + ((lane >> 4) << 3)) * GLD
                    + ((lane >> 3) & 1) * 8) * 2);

    float acc[2][4][4];
    #pragma unroll
    for (int mi = 0; mi < 2; mi++)
        #pragma unroll
        for (int nt = 0; nt < 4; nt++)
            #pragma unroll
            for (int u = 0; u < 4; u++) acc[mi][nt][u] = 0.f;

    stage(0, 0);
    __syncthreads();

    #pragma unroll 1
    for (int kt = 0; kt < 8; kt++) {
        const int buf = kt & 1;
        if (kt < 7) stage((kt + 1) * 64, buf ^ 1);
        const uint32_t a_lane = a_lane0 + (uint32_t)buf * GA_BUF;
        const uint32_t b_lane = b_lane0 + (uint32_t)buf * GA_BUF;
        #pragma unroll
        for (int ks = 0; ks < 4; ks++) {
            uint32_t b[2][4];
            ldmatrix_x4(b[0][0], b[0][1], b[0][2], b[0][3], b_lane + ks * 32);
            ldmatrix_x4(b[1][0], b[1][1], b[1][2], b[1][3],
                        b_lane + 16 * GLD * 2 + ks * 32);
            #pragma unroll
            for (int mi = 0; mi < 2; mi++) {
                uint32_t a0, a1, a2, a3;
                ldmatrix_x4(a0, a1, a2, a3, a_lane + mi * 16 * GLD * 2 + ks * 32);
                mma16816(acc[mi][0], a0, a1, a2, a3, b[0][0], b[0][1]);
                mma16816(acc[mi][1], a0, a1, a2, a3, b[0][2], b[0][3]);
                mma16816(acc[mi][2], a0, a1, a2, a3, b[1][0], b[1][1]);
                mma16816(acc[mi][3], a0, a1, a2, a3, b[1][2], b[1][3]);
            }
        }
        __syncthreads();
    }

    __half* tT = (__half*)smem;
    #pragma unroll
    for (int nt = 0; nt < 4; nt++) {
        int cl = nw * 32 + nt * 8 + ((lane & 3) << 1);
        float2 bb = *(const float2*)&Wb[col0 + cl];
        #pragma unroll
        for (int mi = 0; mi < 2; mi++) {
            int rl0 = mw * 32 + mi * 16 + (lane >> 2);
            int rl1 = rl0 + 8;
            float v00 = acc[mi][nt][0] + bb.x;
            float v01 = acc[mi][nt][1] + bb.y;
            float v10 = acc[mi][nt][2] + bb.x;
            float v11 = acc[mi][nt][3] + bb.y;
            *(float2*)&g_wh[(size_t)(row0 + rl0) * D_OUT + col0 + cl] = make_float2(v00, v01);
            *(float2*)&g_wh[(size_t)(row0 + rl1) * D_OUT + col0 + cl] = make_float2(v10, v11);
            tT[cl * LDT + rl0]       = __float2half(v00);
            tT[(cl + 1) * LDT + rl0] = __float2half(v01);
            tT[cl * LDT + rl1]       = __float2half(v10);
            tT[(cl + 1) * LDT + rl1] = __float2half(v11);
        }
    }
    __syncthreads();
    {
        int c = tid >> 2;
        int seg = (tid & 3) << 5;
        const uint4* src = (const uint4*)(tT + c * LDT + seg);
        uint4* dst = (uint4*)(g_whT + (size_t)(col0 + c) * N_NODES + row0 + seg);
        #pragma unroll
        for (int i = 0; i < 4; i++) dst[i] = src[i];
    }
}

// ==================== Kernel 2: per-row scores (+ global max of t) ==========
__global__ void __launch_bounds__(256) scores_kernel(const float* __restrict__ aw)
{
    const int lane = threadIdx.x & 31;
    const int warp = threadIdx.x >> 5;
    const int row  = blockIdx.x * 8 + warp;

    const float4* whr = (const float4*)&g_wh[(size_t)row * D_OUT];
    float4 w0 = whr[lane * 2];
    float4 w1 = whr[lane * 2 + 1];
    const float4* as = (const float4*)aw;
    const float4* ad = (const float4*)(aw + D_OUT);
    float4 a0 = as[lane * 2], a1 = as[lane * 2 + 1];
    float4 b0 = ad[lane * 2], b1 = ad[lane * 2 + 1];

    float ss = w0.x*a0.x + w0.y*a0.y + w0.z*a0.z + w0.w*a0.w
             + w1.x*a1.x + w1.y*a1.y + w1.z*a1.z + w1.w*a1.w;
    float sd = w0.x*b0.x + w0.y*b0.y + w0.z*b0.z + w0.w*b0.w
             + w1.x*b1.x + w1.y*b1.y + w1.z*b1.z + w1.w*b1.w;
    #pragma unroll
    for (int o = 16; o; o >>= 1) {
        ss += __shfl_xor_sync(0xffffffffu, ss, o);
        sd += __shfl_xor_sync(0xffffffffu, sd, o);
    }
    if (lane == 0) {
        g_ssrc[row] = ss;
        g_t[row]    = sd;
        atomicMax(&g_Tbits, fkey(sd));
    }
}

// ==================== Kernel 2b: elementwise finalize ========================
__global__ void __launch_bounds__(512) finalize_kernel(const float* __restrict__ abp)
{
    const int i = blockIdx.x * 512 + threadIdx.x;
    const float T = finv(g_Tbits);
    const float ab = abp[0];
    float t = g_t[i];
    g_EF[i] = packh2(__expf(t - T), __expf(0.2f * (t - T)));
    float u = g_ssrc[i] + ab + T;
    float M = u > 0.f ? u : 0.2f * u;
    g_alpha[i] = __expf(u - M);
    g_beta[i]  = __expf(0.2f * u - M);
    g_thr[i]   = __expf(-u);
}

// ==================== Kernel 3: HMMA flash (256 thr, occ 2, K-split 2) ======
#define LD 72
static constexpr uint32_t BS_BUF = 256 * LD * 2;          // 36864
static constexpr uint32_t AS_OFF = 2 * BS_BUF;            // 73728
static constexpr uint32_t AS_BUF = MT * LD * 2;           // 9216
static constexpr uint32_t LS_OFF = AS_OFF + 2 * AS_BUF;   // 92160
static constexpr uint32_t SMEM_TOTAL = LS_OFF + 256;      // 92416

__global__ void __launch_bounds__(FTH, 2) flash_mma_kernel(const int* __restrict__ adj)
{
    extern __shared__ __align__(16) char smem[];
    const uint32_t sbase = smem_u32(smem);
    float* lsum_s = (float*)(smem + LS_OFF);

    const int tid  = threadIdx.x;
    const int lane = tid & 31;
    const int warp = tid >> 5;
    const int rb = blockIdx.x >> 1;
    const int kh = blockIdx.x & 1;
    const int rowbase = rb * MT;
    const int kbase = kh * (N_NODES / 2);

    // ---- per-thread P-gen constants: prow = tid/4, pseg = tid%4 (16 j's) ----
    const int prow = tid >> 2;
    const int pseg = tid & 3;
    const int row  = rowbase + prow;
    const float alpha = g_alpha[row];
    const float beta  = g_beta[row];
    const float thr   = g_thr[row];
    float lpriv = 0.f;

    const int* adjrow = adj + (size_t)row * N_NODES + kbase;
    const uint32_t a_st0 = sbase + AS_OFF + (uint32_t)((prow * LD + pseg * 16) * 2);

    // ---- mma addressing: warp grid 2m x 4n (warp tile 32 x 64) ----
    const int mw = warp >> 2;            // 0..1
    const int nw = warp & 3;             // 0..3
    const uint32_t a_lane0 = sbase + AS_OFF +
        (uint32_t)(((mw * 32 + (lane & 15)) * LD + (lane >> 4) * 8) * 2);
    const uint32_t b_lane0 = sbase +
        (uint32_t)(((nw * 64 + (lane & 7) + ((lane >> 4) << 3)) * LD
                    + ((lane >> 3) & 1) * 8) * 2);

    float acc[2][8][4];
    #pragma unroll
    for (int mi = 0; mi < 2; mi++)
        #pragma unroll
        for (int nt = 0; nt < 8; nt++)
            #pragma unroll
            for (int u = 0; u < 4; u++) acc[mi][nt][u] = 0.f;

    // ---- B stage via cp.async: 8 x 16B per thread ----
    auto stageB = [&](int kcL, int buf) {
        const int k0 = kbase + kcL * KC;
        const uint32_t bb = sbase + (uint32_t)buf * BS_BUF;
        #pragma unroll
        for (int i = 0; i < 8; i++) {
            int f = tid + i * FTH;       // 0..2047
            int n = f >> 3;
            int c = (f & 7) * 8;
            cp16(bb + (uint32_t)((n * LD + c) * 2),
                 g_whT + (size_t)n * N_NODES + k0 + c);
        }
    };

    // ---- P-gen: 16 weights; adj from regs, EF via __ldg ----
    auto pgen = [&](int kcL, int buf, const int4* q) {
        const int jb = kbase + kcL * KC + pseg * 16;
        const uint4* ep = (const uint4*)(g_EF + jb);
        uint32_t w[8];
        float ls = 0.f;
        #pragma unroll
        for (int g = 0; g < 4; g++) {
            uint4 e = __ldg(ep + g);
            int4 qq = q[g];
            float2 ef;
            ef = unph2(e.x); float p0 = qq.x > 0 ? (ef.x > thr ? alpha * ef.x : beta * ef.y) : 0.f;
            ef = unph2(e.y); float p1 = qq.y > 0 ? (ef.x > thr ? alpha * ef.x : beta * ef.y) : 0.f;
            ef = unph2(e.z); float p2 = qq.z > 0 ? (ef.x > thr ? alpha * ef.x : beta * ef.y) : 0.f;
            ef = unph2(e.w); float p3 = qq.w > 0 ? (ef.x > thr ? alpha * ef.x : beta * ef.y) : 0.f;
            ls += (p0 + p1) + (p2 + p3);
            w[g * 2]     = packh2(p0, p1);
            w[g * 2 + 1] = packh2(p2, p3);
        }
        lpriv += ls;
        uint32_t dst = a_st0 + (uint32_t)buf * AS_BUF;
        asm volatile("st.shared.v4.b32 [%0], {%1,%2,%3,%4};"
                     :: "r"(dst), "r"(w[0]), "r"(w[1]), "r"(w[2]), "r"(w[3]) : "memory");
        asm volatile("st.shared.v4.b32 [%0], {%1,%2,%3,%4};"
                     :: "r"(dst + 16), "r"(w[4]), "r"(w[5]), "r"(w[6]), "r"(w[7]) : "memory");
    };

    // ---- prologue ----
    stageB(0, 0);
    CP_COMMIT();
    {
        int4 q[4];
        const int4* ap = (const int4*)(adjrow) + pseg * 4;
        q[0] = ap[0]; q[1] = ap[1]; q[2] = ap[2]; q[3] = ap[3];
        pgen(0, 0, q);
    }
    CP_WAIT0();
    __syncthreads();          // Bs[0], As[0] ready

    // ---- main loop: one sync per chunk ----
    #pragma unroll 2
    for (int kcL = 0; kcL < NCHL; kcL++) {
        const int buf = kcL & 1;
        int4 qn[4];
        if (kcL + 1 < NCHL) {
            stageB(kcL + 1, buf ^ 1);
            CP_COMMIT();
            const int4* ap = (const int4*)(adjrow + (kcL + 1) * KC) + pseg * 4;
            qn[0] = ap[0]; qn[1] = ap[1]; qn[2] = ap[2]; qn[3] = ap[3];
        }

        const uint32_t a_lane = a_lane0 + (uint32_t)buf * AS_BUF;
        const uint32_t b_lane = b_lane0 + (uint32_t)buf * BS_BUF;
        #pragma unroll
        for (int ks = 0; ks < 4; ks++) {
            uint32_t bf[4][4];
            #pragma unroll
            for (int g = 0; g < 4; g++)
                ldmatrix_x4(bf[g][0], bf[g][1], bf[g][2], bf[g][3],
                            b_lane + (uint32_t)(g * 16 * LD * 2 + ks * 32));
            #pragma unroll
            for (int mi = 0; mi < 2; mi++) {
                uint32_t a0, a1, a2, a3;
                ldmatrix_x4(a0, a1, a2, a3,
                            a_lane + (uint32_t)(mi * 16 * LD * 2 + ks * 32));
                #pragma unroll
                for (int g = 0; g < 4; g++) {
                    mma16816(acc[mi][g * 2],     a0, a1, a2, a3, bf[g][0], bf[g][1]);
                    mma16816(acc[mi][g * 2 + 1], a0, a1, a2, a3, bf[g][2], bf[g][3]);
                }
            }
        }
        if (kcL + 1 < NCHL) pgen(kcL + 1, buf ^ 1, qn);
        CP_WAIT0();
        __syncthreads();
    }

    // ---- lsum partial: reduce over 4 threads sharing a row ----
    lpriv += __shfl_xor_sync(0xffffffffu, lpriv, 1);
    lpriv += __shfl_xor_sync(0xffffffffu, lpriv, 2);
    if ((lane & 3) == 0) lsum_s[prow] = lpriv;
    __syncthreads();
    if (tid < MT) g_plsum[kh * N_NODES + rowbase + tid] = lsum_s[tid];

    // ---- write raw partial acc ----
    float* pout = g_pacc + (size_t)kh * N_NODES * D_OUT;
    #pragma unroll
    for (int mi = 0; mi < 2; mi++) {
        int r0 = mw * 32 + mi * 16 + (lane >> 2);
        int r1 = r0 + 8;
        #pragma unroll
        for (int nt = 0; nt < 8; nt++) {
            int c = nw * 64 + nt * 8 + ((lane & 3) << 1);
            *(float2*)&pout[(size_t)(rowbase + r0) * D_OUT + c] =
                make_float2(acc[mi][nt][0], acc[mi][nt][1]);
            *(float2*)&pout[(size_t)(rowbase + r1) * D_OUT + c] =
                make_float2(acc[mi][nt][2], acc[mi][nt][3]);
        }
    }
}

// ==================== Kernel 4: combine partials ============================
__global__ void __launch_bounds__(512) reduce_kernel(float* __restrict__ out)
{
    const int idx = blockIdx.x * 512 + threadIdx.x;   // float4 index
    const int row = idx >> 6;
    const float inv = 1.f / (g_plsum[row] + g_plsum[N_NODES + row]);
    float4 a = ((const float4*)g_pacc)[idx];
    float4 b = ((const float4*)g_pacc)[N_NODES * D_OUT / 4 + idx];
    float4 o;
    o.x = (a.x + b.x) * inv;
    o.y = (a.y + b.y) * inv;
    o.z = (a.z + b.z) * inv;
    o.w = (a.w + b.w) * inv;
    ((float4*)out)[idx] = o;
}

// ==================== launch ================================================
extern "C" void kernel_launch(void* const* d_in, const int* in_sizes, int n_in,
                              void* d_out, int out_size)
{
    const float* h   = (const float*)d_in[0];
    const int*   adj = (const int*)  d_in[1];
    const float* Ww  = (const float*)d_in[2];
    const float* Wb  = (const float*)d_in[3];
    const float* aw  = (const float*)d_in[4];
    const float* ab  = (const float*)d_in[5];
    float* out = (float*)d_out;

    cudaFuncSetAttribute(gemm_wh_kernel,
                         cudaFuncAttributeMaxDynamicSharedMemorySize, GEMM_SMEM);
    cudaFuncSetAttribute(flash_mma_kernel,
                         cudaFuncAttributeMaxDynamicSharedMemorySize, SMEM_TOTAL);

    gemm_wh_kernel<<<dim3(D_OUT / 128, N_NODES / 128), 512, GEMM_SMEM>>>(h, Ww, Wb);
    scores_kernel<<<N_NODES / 8, 256>>>(aw);
    finalize_kernel<<<N_NODES / 512, 512>>>(ab);
    flash_mma_kernel<<<(N_NODES / MT) * 2, FTH, SMEM_TOTAL>>>(adj);
    reduce_kernel<<<N_NODES * D_OUT / 4 / 512, 512>>>(out);
}

// round 15
// speedup vs baseline: 1.1496x; 1.0585x over previous
#include <cuda_runtime.h>
#include <cuda_fp16.h>
#include <cstdint>

#define N_NODES 8192
#define D_IN    512
#define D_OUT   256
#define KC      64
#define NCH     (N_NODES / KC)
#define MT      64
#define FTH     512

// ---------------- scratch (device globals) ----------------------------------
static __device__ float    g_wh [N_NODES * D_OUT];   // fp32 wh (8 MB)
static __device__ __half   g_whT[D_OUT * N_NODES];   // fp16 wh^T (4 MB)
static __device__ float    g_ssrc[N_NODES];
static __device__ float    g_t[N_NODES];
static __device__ uint32_t g_EF[N_NODES];            // half2 {E, F}
static __device__ float    g_alpha[N_NODES];
static __device__ float    g_beta[N_NODES];
static __device__ float    g_thr[N_NODES];
static __device__ unsigned g_Tbits;

// ---------------- PTX helpers -----------------------------------------------
__device__ __forceinline__ uint32_t smem_u32(const void* p) {
    uint32_t a;
    asm("{ .reg .u64 t; cvta.to.shared.u64 t, %1; cvt.u32.u64 %0, t; }"
        : "=r"(a) : "l"(p));
    return a;
}
__device__ __forceinline__ void ldmatrix_x4(uint32_t& r0, uint32_t& r1,
                                            uint32_t& r2, uint32_t& r3,
                                            uint32_t addr) {
    asm volatile("ldmatrix.sync.aligned.m8n8.x4.shared.b16 {%0,%1,%2,%3}, [%4];"
                 : "=r"(r0), "=r"(r1), "=r"(r2), "=r"(r3) : "r"(addr));
}
__device__ __forceinline__ void mma16816(float* c,
                                         uint32_t a0, uint32_t a1, uint32_t a2, uint32_t a3,
                                         uint32_t b0, uint32_t b1) {
    asm volatile("mma.sync.aligned.m16n8k16.row.col.f32.f16.f16.f32 "
                 "{%0,%1,%2,%3}, {%4,%5,%6,%7}, {%8,%9}, {%0,%1,%2,%3};"
                 : "+f"(c[0]), "+f"(c[1]), "+f"(c[2]), "+f"(c[3])
                 : "r"(a0), "r"(a1), "r"(a2), "r"(a3), "r"(b0), "r"(b1));
}
__device__ __forceinline__ void cp16(uint32_t dst, const void* src) {
    asm volatile("cp.async.ca.shared.global [%0], [%1], 16;"
                 :: "r"(dst), "l"(src) : "memory");
}
#define CP_COMMIT() asm volatile("cp.async.commit_group;" ::: "memory")
#define CP_WAIT0()  asm volatile("cp.async.wait_group 0;" ::: "memory")
#define CP_WAIT1()  asm volatile("cp.async.wait_group 1;" ::: "memory")

__device__ __forceinline__ unsigned fkey(float x) {
    int i = __float_as_int(x);
    return i >= 0 ? ((unsigned)i | 0x80000000u) : ~(unsigned)i;
}
__device__ __forceinline__ float finv(unsigned k) {
    return (k & 0x80000000u) ? __int_as_float((int)(k & 0x7fffffffu))
                             : __int_as_float((int)~k);
}
__device__ __forceinline__ uint32_t packh2(float a, float b) {
    __half2 h = __floats2half2_rn(a, b);
    return *(uint32_t*)&h;
}
__device__ __forceinline__ float2 unph2(uint32_t u) {
    return __half22float2(*(__half2*)&u);
}

// ==================== Kernel 1: wh = h @ W^T + b  (HMMA fp16) ===============
#define GLD 72
static constexpr uint32_t GA_BUF = 128 * GLD * 2;
static constexpr uint32_t GB_OFF = 2 * GA_BUF;
static constexpr uint32_t GEMM_SMEM = 4 * GA_BUF;
#define LDT 136

__global__ void __launch_bounds__(512) gemm_wh_kernel(
    const float* __restrict__ h, const float* __restrict__ W,
    const float* __restrict__ Wb)
{
    extern __shared__ __align__(16) char smem[];
    const uint32_t sbase = smem_u32(smem);
    const int tid  = threadIdx.x;
    const int lane = tid & 31;
    const int warp = tid >> 5;
    const int mw = warp >> 2;
    const int nw = warp & 3;
    const int row0 = blockIdx.y * 128;
    const int col0 = blockIdx.x * 128;

    if (blockIdx.x == 0 && blockIdx.y == 0 && tid == 0) g_Tbits = 0u;

    auto stage = [&](int kb, int buf) {
        __half* Ah = (__half*)(smem + buf * GA_BUF);
        __half* Bh = (__half*)(smem + GB_OFF + buf * GA_BUF);
        #pragma unroll
        for (int i = 0; i < 4; i++) {
            int f = tid + i * 512;
            int r = f >> 4;
            int c4 = (f & 15) << 2;
            float4 v = *(const float4*)&h[(size_t)(row0 + r) * D_IN + kb + c4];
            *(uint2*)(Ah + r * GLD + c4) = make_uint2(packh2(v.x, v.y), packh2(v.z, v.w));
            float4 u = *(const float4*)&W[(size_t)(col0 + r) * D_IN + kb + c4];
            *(uint2*)(Bh + r * GLD + c4) = make_uint2(packh2(u.x, u.y), packh2(u.z, u.w));
        }
    };

    const uint32_t a_lane0 = sbase +
        (uint32_t)(((mw * 32 + (lane & 15)) * GLD + (lane >> 4) * 8) * 2);
    const uint32_t b_lane0 = sbase + GB_OFF +
        (uint32_t)(((nw * 32 + (lane & 7) + ((lane >> 4) << 3)) * GLD
                    + ((lane >> 3) & 1) * 8) * 2);

    float acc[2][4][4];
    #pragma unroll
    for (int mi = 0; mi < 2; mi++)
        #pragma unroll
        for (int nt = 0; nt < 4; nt++)
            #pragma unroll
            for (int u = 0; u < 4; u++) acc[mi][nt][u] = 0.f;

    stage(0, 0);
    __syncthreads();

    #pragma unroll 1
    for (int kt = 0; kt < 8; kt++) {
        const int buf = kt & 1;
        if (kt < 7) stage((kt + 1) * 64, buf ^ 1);
        const uint32_t a_lane = a_lane0 + (uint32_t)buf * GA_BUF;
        const uint32_t b_lane = b_lane0 + (uint32_t)buf * GA_BUF;
        #pragma unroll
        for (int ks = 0; ks < 4; ks++) {
            uint32_t b[2][4];
            ldmatrix_x4(b[0][0], b[0][1], b[0][2], b[0][3], b_lane + ks * 32);
            ldmatrix_x4(b[1][0], b[1][1], b[1][2], b[1][3],
                        b_lane + 16 * GLD * 2 + ks * 32);
            #pragma unroll
            for (int mi = 0; mi < 2; mi++) {
                uint32_t a0, a1, a2, a3;
                ldmatrix_x4(a0, a1, a2, a3, a_lane + mi * 16 * GLD * 2 + ks * 32);
                mma16816(acc[mi][0], a0, a1, a2, a3, b[0][0], b[0][1]);
                mma16816(acc[mi][1], a0, a1, a2, a3, b[0][2], b[0][3]);
                mma16816(acc[mi][2], a0, a1, a2, a3, b[1][0], b[1][1]);
                mma16816(acc[mi][3], a0, a1, a2, a3, b[1][2], b[1][3]);
            }
        }
        __syncthreads();
    }

    __half* tT = (__half*)smem;
    #pragma unroll
    for (int nt = 0; nt < 4; nt++) {
        int cl = nw * 32 + nt * 8 + ((lane & 3) << 1);
        float2 bb = *(const float2*)&Wb[col0 + cl];
        #pragma unroll
        for (int mi = 0; mi < 2; mi++) {
            int rl0 = mw * 32 + mi * 16 + (lane >> 2);
            int rl1 = rl0 + 8;
            float v00 = acc[mi][nt][0] + bb.x;
            float v01 = acc[mi][nt][1] + bb.y;
            float v10 = acc[mi][nt][2] + bb.x;
            float v11 = acc[mi][nt][3] + bb.y;
            *(float2*)&g_wh[(size_t)(row0 + rl0) * D_OUT + col0 + cl] = make_float2(v00, v01);
            *(float2*)&g_wh[(size_t)(row0 + rl1) * D_OUT + col0 + cl] = make_float2(v10, v11);
            tT[cl * LDT + rl0]       = __float2half(v00);
            tT[(cl + 1) * LDT + rl0] = __float2half(v01);
            tT[cl * LDT + rl1]       = __float2half(v10);
            tT[(cl + 1) * LDT + rl1] = __float2half(v11);
        }
    }
    __syncthreads();
    {
        int c = tid >> 2;
        int seg = (tid & 3) << 5;
        const uint4* src = (const uint4*)(tT + c * LDT + seg);
        uint4* dst = (uint4*)(g_whT + (size_t)(col0 + c) * N_NODES + row0 + seg);
        #pragma unroll
        for (int i = 0; i < 4; i++) dst[i] = src[i];
    }
}

// ==================== Kernel 2: per-row scores (+ global max of t) ==========
__global__ void __launch_bounds__(256) scores_kernel(const float* __restrict__ aw)
{
    const int lane = threadIdx.x & 31;
    const int warp = threadIdx.x >> 5;
    const int row  = blockIdx.x * 8 + warp;

    const float4* whr = (const float4*)&g_wh[(size_t)row * D_OUT];
    float4 w0 = whr[lane * 2];
    float4 w1 = whr[lane * 2 + 1];
    const float4* as = (const float4*)aw;
    const float4* ad = (const float4*)(aw + D_OUT);
    float4 a0 = as[lane * 2], a1 = as[lane * 2 + 1];
    float4 b0 = ad[lane * 2], b1 = ad[lane * 2 + 1];

    float ss = w0.x*a0.x + w0.y*a0.y + w0.z*a0.z + w0.w*a0.w
             + w1.x*a1.x + w1.y*a1.y + w1.z*a1.z + w1.w*a1.w;
    float sd = w0.x*b0.x + w0.y*b0.y + w0.z*b0.z + w0.w*b0.w
             + w1.x*b1.x + w1.y*b1.y + w1.z*b1.z + w1.w*b1.w;
    #pragma unroll
    for (int o = 16; o; o >>= 1) {
        ss += __shfl_xor_sync(0xffffffffu, ss, o);
        sd += __shfl_xor_sync(0xffffffffu, sd, o);
    }
    if (lane == 0) {
        g_ssrc[row] = ss;
        g_t[row]    = sd;
        atomicMax(&g_Tbits, fkey(sd));
    }
}

// ==================== Kernel 2b: elementwise finalize ========================
__global__ void __launch_bounds__(512) finalize_kernel(const float* __restrict__ abp)
{
    const int i = blockIdx.x * 512 + threadIdx.x;
    const float T = finv(g_Tbits);
    const float ab = abp[0];
    float t = g_t[i];
    g_EF[i] = packh2(__expf(t - T), __expf(0.2f * (t - T)));
    float u = g_ssrc[i] + ab + T;
    float M = u > 0.f ? u : 0.2f * u;
    g_alpha[i] = __expf(u - M);
    g_beta[i]  = __expf(0.2f * u - M);
    g_thr[i]   = __expf(-u);
}

// ==================== Kernel 3: HMMA flash (R8 core, 2-deep pipeline) =======
#define LD 72                                   // halves per smem row (144 B)
static constexpr uint32_t BS_BUF = 256 * LD * 2;          // 36864
static constexpr uint32_t AS_OFF = 3 * BS_BUF;            // 110592
static constexpr uint32_t AS_BUF = MT * LD * 2;           // 9216
static constexpr uint32_t EF_OFF = AS_OFF + 3 * AS_BUF;   // 138240
static constexpr uint32_t LS_OFF = EF_OFF + N_NODES * 4;  // 171008
static constexpr uint32_t SMEM_TOTAL = LS_OFF + 256;      // 171264

__global__ void __launch_bounds__(FTH) flash_mma_kernel(
    const int* __restrict__ adj, float* __restrict__ out)
{
    extern __shared__ __align__(16) char smem[];
    const uint32_t sbase = smem_u32(smem);
    uint32_t* EFs = (uint32_t*)(smem + EF_OFF);
    float* lsum_s = (float*)(smem + LS_OFF);

    const int tid  = threadIdx.x;
    const int lane = tid & 31;
    const int warp = tid >> 5;
    const int rowbase = blockIdx.x * MT;

    // ---- prestage EF (32 KB) ----
    #pragma unroll
    for (int i = 0; i < 4; i++) {
        int f = tid + i * FTH;
        ((uint4*)EFs)[f] = ((const uint4*)g_EF)[f];
    }

    // ---- per-thread P-gen constants ----
    const int prow = tid >> 3;           // 0..63
    const int pseg = tid & 7;            // 8 j's each
    const int row  = rowbase + prow;
    const float alpha = g_alpha[row];
    const float beta  = g_beta[row];
    const float thr   = g_thr[row];
    float lpriv = 0.f;

    const int* adjrow = adj + (size_t)row * N_NODES;
    const uint32_t a_st0 = sbase + AS_OFF + (uint32_t)((prow * LD + pseg * 8) * 2);

    // ---- mma addressing: warp grid 2m x 8n ----
    const int mw = warp >> 3;
    const int nw = warp & 7;
    const uint32_t a_lane0 = sbase + AS_OFF +
        (uint32_t)(((mw * 32 + (lane & 15)) * LD + (lane >> 4) * 8) * 2);
    const uint32_t b_lane0 = sbase +
        (uint32_t)(((nw * 32 + (lane & 7) + ((lane >> 4) << 3)) * LD
                    + (((lane >> 3) & 1) << 3)) * 2);

    float acc[2][4][4];
    #pragma unroll
    for (int mi = 0; mi < 2; mi++)
        #pragma unroll
        for (int nt = 0; nt < 4; nt++)
            #pragma unroll
            for (int u = 0; u < 4; u++) acc[mi][nt][u] = 0.f;

    auto stageB = [&](int kc, int buf) {
        const int k0 = kc * KC;
        const uint32_t bb = sbase + (uint32_t)buf * BS_BUF;
        #pragma unroll
        for (int i = 0; i < 4; i++) {
            int f = tid + i * FTH;
            int n = f >> 3;
            int c = (f & 7) * 8;
            cp16(bb + (uint32_t)((n * LD + c) * 2),
                 g_whT + (size_t)n * N_NODES + k0 + c);
        }
    };

    // ---- P-gen from prefetched adj regs + half2 EF table ----
    auto pgen = [&](int kc, int buf, int4 q0, int4 q1) {
        const int jb = kc * KC + pseg * 8;
        uint4 u0 = *(const uint4*)(EFs + jb);
        uint4 u1 = *(const uint4*)(EFs + jb + 4);
        float2 ef;
        ef = unph2(u0.x); float p0 = q0.x > 0 ? (ef.x > thr ? alpha * ef.x : beta * ef.y) : 0.f;
        ef = unph2(u0.y); float p1 = q0.y > 0 ? (ef.x > thr ? alpha * ef.x : beta * ef.y) : 0.f;
        ef = unph2(u0.z); float p2 = q0.z > 0 ? (ef.x > thr ? alpha * ef.x : beta * ef.y) : 0.f;
        ef = unph2(u0.w); float p3 = q0.w > 0 ? (ef.x > thr ? alpha * ef.x : beta * ef.y) : 0.f;
        ef = unph2(u1.x); float p4 = q1.x > 0 ? (ef.x > thr ? alpha * ef.x : beta * ef.y) : 0.f;
        ef = unph2(u1.y); float p5 = q1.y > 0 ? (ef.x > thr ? alpha * ef.x : beta * ef.y) : 0.f;
        ef = unph2(u1.z); float p6 = q1.z > 0 ? (ef.x > thr ? alpha * ef.x : beta * ef.y) : 0.f;
        ef = unph2(u1.w); float p7 = q1.w > 0 ? (ef.x > thr ? alpha * ef.x : beta * ef.y) : 0.f;
        lpriv += ((p0 + p1) + (p2 + p3)) + ((p4 + p5) + (p6 + p7));
        uint4 w;
        w.x = packh2(p0, p1); w.y = packh2(p2, p3);
        w.z = packh2(p4, p5); w.w = packh2(p6, p7);
        uint32_t dst = a_st0 + (uint32_t)buf * AS_BUF;
        asm volatile("st.shared.v4.b32 [%0], {%1,%2,%3,%4};"
                     :: "r"(dst), "r"(w.x), "r"(w.y), "r"(w.z), "r"(w.w) : "memory");
    };

    auto ld_frags = [&](uint32_t a_lane, uint32_t b_lane, int ks,
                        uint32_t (*af)[4], uint32_t (*bf)[4]) {
        ldmatrix_x4(bf[0][0], bf[0][1], bf[0][2], bf[0][3],
                    b_lane + (uint32_t)(ks * 32));
        ldmatrix_x4(bf[1][0], bf[1][1], bf[1][2], bf[1][3],
                    b_lane + (uint32_t)(16 * LD * 2 + ks * 32));
        ldmatrix_x4(af[0][0], af[0][1], af[0][2], af[0][3],
                    a_lane + (uint32_t)(ks * 32));
        ldmatrix_x4(af[1][0], af[1][1], af[1][2], af[1][3],
                    a_lane + (uint32_t)(16 * LD * 2 + ks * 32));
    };

    // ---- prologue: fill two stages ahead ----
    stageB(0, 0);
    CP_COMMIT();
    stageB(1, 1);
    CP_COMMIT();
    __syncthreads();          // EFs visible
    {
        const int4* ap = (const int4*)(adjrow) + pseg * 2;
        pgen(0, 0, ap[0], ap[1]);
        const int4* ap1 = (const int4*)(adjrow + KC) + pseg * 2;
        pgen(1, 1, ap1[0], ap1[1]);
    }
    CP_WAIT1();               // Bs[0] done (Bs[1] may be in flight)
    __syncthreads();          // Bs[0], As[0], As[1] visible

    // ---- main loop: everything staged 2 chunks ahead ----
    int bufA = 0, bufW = 2;
    #pragma unroll 1
    for (int kt = 0; kt < NCH; kt++) {
        const bool have2 = (kt + 2 < NCH);
        int4 qn0, qn1;
        if (have2) {
            stageB(kt + 2, bufW);
            CP_COMMIT();
            const int4* ap = (const int4*)(adjrow + (kt + 2) * KC) + pseg * 2;
            qn0 = ap[0]; qn1 = ap[1];
        }

        const uint32_t a_lane = a_lane0 + (uint32_t)bufA * AS_BUF;
        const uint32_t b_lane = b_lane0 + (uint32_t)bufA * BS_BUF;

        uint32_t af[2][2][4], bf[2][2][4];
        ld_frags(a_lane, b_lane, 0, af[0], bf[0]);
        #pragma unroll
        for (int ks = 0; ks < 4; ks++) {
            const int par = ks & 1;
            if (ks < 3) ld_frags(a_lane, b_lane, ks + 1, af[par ^ 1], bf[par ^ 1]);
            #pragma unroll
            for (int mi = 0; mi < 2; mi++) {
                mma16816(acc[mi][0], af[par][mi][0], af[par][mi][1],
                         af[par][mi][2], af[par][mi][3], bf[par][0][0], bf[par][0][1]);
                mma16816(acc[mi][1], af[par][mi][0], af[par][mi][1],
                         af[par][mi][2], af[par][mi][3], bf[par][0][2], bf[par][0][3]);
                mma16816(acc[mi][2], af[par][mi][0], af[par][mi][1],
                         af[par][mi][2], af[par][mi][3], bf[par][1][0], bf[par][1][1]);
                mma16816(acc[mi][3], af[par][mi][0], af[par][mi][1],
                         af[par][mi][2], af[par][mi][3], bf[par][1][2], bf[par][1][3]);
            }
        }
        if (have2) {
            pgen(kt + 2, bufW, qn0, qn1);
            CP_WAIT1();       // ensure chunk kt+1's B landed; kt+2's may fly
        } else {
            CP_WAIT0();
        }
        __syncthreads();
        bufA = (bufA == 2) ? 0 : bufA + 1;
        bufW = (bufW == 2) ? 0 : bufW + 1;
    }

    // ---- lsum ----
    lpriv += __shfl_xor_sync(0xffffffffu, lpriv, 1);
    lpriv += __shfl_xor_sync(0xffffffffu, lpriv, 2);
    lpriv += __shfl_xor_sync(0xffffffffu, lpriv, 4);
    if ((lane & 7) == 0) lsum_s[prow] = lpriv;
    __syncthreads();

    // ---- write out ----
    #pragma unroll
    for (int mi = 0; mi < 2; mi++) {
        int r0 = mw * 32 + mi * 16 + (lane >> 2);
        int r1 = r0 + 8;
        float inv0 = 1.f / lsum_s[r0];
        float inv1 = 1.f / lsum_s[r1];
        #pragma unroll
        for (int nt = 0; nt < 4; nt++) {
            int c = nw * 32 + nt * 8 + ((lane & 3) << 1);
            float2 v0 = make_float2(acc[mi][nt][0] * inv0, acc[mi][nt][1] * inv0);
            float2 v1 = make_float2(acc[mi][nt][2] * inv1, acc[mi][nt][3] * inv1);
            *(float2*)&out[(size_t)(rowbase + r0) * D_OUT + c] = v0;
            *(float2*)&out[(size_t)(rowbase + r1) * D_OUT + c] = v1;
        }
    }
}

// ==================== launch ================================================
extern "C" void kernel_launch(void* const* d_in, const int* in_sizes, int n_in,
                              void* d_out, int out_size)
{
    const float* h   = (const float*)d_in[0];
    const int*   adj = (const int*)  d_in[1];
    const float* Ww  = (const float*)d_in[2];
    const float* Wb  = (const float*)d_in[3];
    const float* aw  = (const float*)d_in[4];
    const float* ab  = (const float*)d_in[5];
    float* out = (float*)d_out;

    cudaFuncSetAttribute(gemm_wh_kernel,
                         cudaFuncAttributeMaxDynamicSharedMemorySize, GEMM_SMEM);
    cudaFuncSetAttribute(flash_mma_kernel,
                         cudaFuncAttributeMaxDynamicSharedMemorySize, SMEM_TOTAL);

    gemm_wh_kernel<<<dim3(D_OUT / 128, N_NODES / 128), 512, GEMM_SMEM>>>(h, Ww, Wb);
    scores_kernel<<<N_NODES / 8, 256>>>(aw);
    finalize_kernel<<<N_NODES / 512, 512>>>(ab);
    flash_mma_kernel<<<N_NODES / MT, FTH, SMEM_TOTAL>>>(adj, out);
}

// round 16
// speedup vs baseline: 1.3467x; 1.1714x over previous
#include <cuda_runtime.h>
#include <cuda_fp16.h>
#include <cstdint>

#define N_NODES 8192
#define D_IN    512
#define D_OUT   256
#define KC      64
#define NCH     (N_NODES / KC)
#define MT      64
#define FTH     512

// ---------------- scratch (device globals) ----------------------------------
static __device__ float    g_wh [N_NODES * D_OUT];   // fp32 wh (8 MB)
static __device__ __half   g_whT[D_OUT * N_NODES];   // fp16 wh^T (4 MB)
static __device__ float    g_ssrc[N_NODES];
static __device__ float    g_t[N_NODES];
static __device__ unsigned g_Tbits;

// ---------------- PTX helpers -----------------------------------------------
__device__ __forceinline__ uint32_t smem_u32(const void* p) {
    uint32_t a;
    asm("{ .reg .u64 t; cvta.to.shared.u64 t, %1; cvt.u32.u64 %0, t; }"
        : "=r"(a) : "l"(p));
    return a;
}
__device__ __forceinline__ void ldmatrix_x4(uint32_t& r0, uint32_t& r1,
                                            uint32_t& r2, uint32_t& r3,
                                            uint32_t addr) {
    asm volatile("ldmatrix.sync.aligned.m8n8.x4.shared.b16 {%0,%1,%2,%3}, [%4];"
                 : "=r"(r0), "=r"(r1), "=r"(r2), "=r"(r3) : "r"(addr));
}
__device__ __forceinline__ void mma16816(float* c,
                                         uint32_t a0, uint32_t a1, uint32_t a2, uint32_t a3,
                                         uint32_t b0, uint32_t b1) {
    asm volatile("mma.sync.aligned.m16n8k16.row.col.f32.f16.f16.f32 "
                 "{%0,%1,%2,%3}, {%4,%5,%6,%7}, {%8,%9}, {%0,%1,%2,%3};"
                 : "+f"(c[0]), "+f"(c[1]), "+f"(c[2]), "+f"(c[3])
                 : "r"(a0), "r"(a1), "r"(a2), "r"(a3), "r"(b0), "r"(b1));
}
__device__ __forceinline__ void cp16(uint32_t dst, const void* src) {
    asm volatile("cp.async.ca.shared.global [%0], [%1], 16;"
                 :: "r"(dst), "l"(src) : "memory");
}
#define CP_COMMIT() asm volatile("cp.async.commit_group;" ::: "memory")
#define CP_WAIT0()  asm volatile("cp.async.wait_group 0;" ::: "memory")

__device__ __forceinline__ unsigned fkey(float x) {
    int i = __float_as_int(x);
    return i >= 0 ? ((unsigned)i | 0x80000000u) : ~(unsigned)i;
}
__device__ __forceinline__ float finv(unsigned k) {
    return (k & 0x80000000u) ? __int_as_float((int)(k & 0x7fffffffu))
                             : __int_as_float((int)~k);
}
__device__ __forceinline__ uint32_t packh2(float a, float b) {
    __half2 h = __floats2half2_rn(a, b);
    return *(uint32_t*)&h;
}
__device__ __forceinline__ float2 unph2(uint32_t u) {
    return __half22float2(*(__half2*)&u);
}

// ==================== Kernel 1: wh = h @ W^T + b  (HMMA fp16) ===============
#define GLD 72
static constexpr uint32_t GA_BUF = 128 * GLD * 2;
static constexpr uint32_t GB_OFF = 2 * GA_BUF;
static constexpr uint32_t GEMM_SMEM = 4 * GA_BUF;
#define LDT 136

__global__ void __launch_bounds__(512) gemm_wh_kernel(
    const float* __restrict__ h, const float* __restrict__ W,
    const float* __restrict__ Wb)
{
    extern __shared__ __align__(16) char smem[];
    const uint32_t sbase = smem_u32(smem);
    const int tid  = threadIdx.x;
    const int lane = tid & 31;
    const int warp = tid >> 5;
    const int mw = warp >> 2;
    const int nw = warp & 3;
    const int row0 = blockIdx.y * 128;
    const int col0 = blockIdx.x * 128;

    if (blockIdx.x == 0 && blockIdx.y == 0 && tid == 0) g_Tbits = 0u;

    auto stage = [&](int kb, int buf) {
        __half* Ah = (__half*)(smem + buf * GA_BUF);
        __half* Bh = (__half*)(smem + GB_OFF + buf * GA_BUF);
        #pragma unroll
        for (int i = 0; i < 4; i++) {
            int f = tid + i * 512;
            int r = f >> 4;
            int c4 = (f & 15) << 2;
            float4 v = *(const float4*)&h[(size_t)(row0 + r) * D_IN + kb + c4];
            *(uint2*)(Ah + r * GLD + c4) = make_uint2(packh2(v.x, v.y), packh2(v.z, v.w));
            float4 u = *(const float4*)&W[(size_t)(col0 + r) * D_IN + kb + c4];
            *(uint2*)(Bh + r * GLD + c4) = make_uint2(packh2(u.x, u.y), packh2(u.z, u.w));
        }
    };

    const uint32_t a_lane0 = sbase +
        (uint32_t)(((mw * 32 + (lane & 15)) * GLD + (lane >> 4) * 8) * 2);
    const uint32_t b_lane0 = sbase + GB_OFF +
        (uint32_t)(((nw * 32 + (lane & 7) + ((lane >> 4) << 3)) * GLD
                    + ((lane >> 3) & 1) * 8) * 2);

    float acc[2][4][4];
    #pragma unroll
    for (int mi = 0; mi < 2; mi++)
        #pragma unroll
        for (int nt = 0; nt < 4; nt++)
            #pragma unroll
            for (int u = 0; u < 4; u++) acc[mi][nt][u] = 0.f;

    stage(0, 0);
    __syncthreads();

    #pragma unroll 1
    for (int kt = 0; kt < 8; kt++) {
        const int buf = kt & 1;
        if (kt < 7) stage((kt + 1) * 64, buf ^ 1);
        const uint32_t a_lane = a_lane0 + (uint32_t)buf * GA_BUF;
        const uint32_t b_lane = b_lane0 + (uint32_t)buf * GA_BUF;
        #pragma unroll
        for (int ks = 0; ks < 4; ks++) {
            uint32_t b[2][4];
            ldmatrix_x4(b[0][0], b[0][1], b[0][2], b[0][3], b_lane + ks * 32);
            ldmatrix_x4(b[1][0], b[1][1], b[1][2], b[1][3],
                        b_lane + 16 * GLD * 2 + ks * 32);
            #pragma unroll
            for (int mi = 0; mi < 2; mi++) {
                uint32_t a0, a1, a2, a3;
                ldmatrix_x4(a0, a1, a2, a3, a_lane + mi * 16 * GLD * 2 + ks * 32);
                mma16816(acc[mi][0], a0, a1, a2, a3, b[0][0], b[0][1]);
                mma16816(acc[mi][1], a0, a1, a2, a3, b[0][2], b[0][3]);
                mma16816(acc[mi][2], a0, a1, a2, a3, b[1][0], b[1][1]);
                mma16816(acc[mi][3], a0, a1, a2, a3, b[1][2], b[1][3]);
            }
        }
        __syncthreads();
    }

    __half* tT = (__half*)smem;
    #pragma unroll
    for (int nt = 0; nt < 4; nt++) {
        int cl = nw * 32 + nt * 8 + ((lane & 3) << 1);
        float2 bb = *(const float2*)&Wb[col0 + cl];
        #pragma unroll
        for (int mi = 0; mi < 2; mi++) {
            int rl0 = mw * 32 + mi * 16 + (lane >> 2);
            int rl1 = rl0 + 8;
            float v00 = acc[mi][nt][0] + bb.x;
            float v01 = acc[mi][nt][1] + bb.y;
            float v10 = acc[mi][nt][2] + bb.x;
            float v11 = acc[mi][nt][3] + bb.y;
            *(float2*)&g_wh[(size_t)(row0 + rl0) * D_OUT + col0 + cl] = make_float2(v00, v01);
            *(float2*)&g_wh[(size_t)(row0 + rl1) * D_OUT + col0 + cl] = make_float2(v10, v11);
            tT[cl * LDT + rl0]       = __float2half(v00);
            tT[(cl + 1) * LDT + rl0] = __float2half(v01);
            tT[cl * LDT + rl1]       = __float2half(v10);
            tT[(cl + 1) * LDT + rl1] = __float2half(v11);
        }
    }
    __syncthreads();
    {
        int c = tid >> 2;
        int seg = (tid & 3) << 5;
        const uint4* src = (const uint4*)(tT + c * LDT + seg);
        uint4* dst = (uint4*)(g_whT + (size_t)(col0 + c) * N_NODES + row0 + seg);
        #pragma unroll
        for (int i = 0; i < 4; i++) dst[i] = src[i];
    }
}

// ==================== Kernel 2: per-row scores (+ global max of t) ==========
__global__ void __launch_bounds__(256) scores_kernel(const float* __restrict__ aw)
{
    __shared__ float red[8];
    const int lane = threadIdx.x & 31;
    const int warp = threadIdx.x >> 5;
    const int row  = blockIdx.x * 8 + warp;

    const float4* whr = (const float4*)&g_wh[(size_t)row * D_OUT];
    float4 w0 = whr[lane * 2];
    float4 w1 = whr[lane * 2 + 1];
    const float4* as = (const float4*)aw;
    const float4* ad = (const float4*)(aw + D_OUT);
    float4 a0 = as[lane * 2], a1 = as[lane * 2 + 1];
    float4 b0 = ad[lane * 2], b1 = ad[lane * 2 + 1];

    float ss = w0.x*a0.x + w0.y*a0.y + w0.z*a0.z + w0.w*a0.w
             + w1.x*a1.x + w1.y*a1.y + w1.z*a1.z + w1.w*a1.w;
    float sd = w0.x*b0.x + w0.y*b0.y + w0.z*b0.z + w0.w*b0.w
             + w1.x*b1.x + w1.y*b1.y + w1.z*b1.z + w1.w*b1.w;
    #pragma unroll
    for (int o = 16; o; o >>= 1) {
        ss += __shfl_xor_sync(0xffffffffu, ss, o);
        sd += __shfl_xor_sync(0xffffffffu, sd, o);
    }
    if (lane == 0) {
        g_ssrc[row] = ss;
        g_t[row]    = sd;
        red[warp]   = sd;
    }
    __syncthreads();
    if (threadIdx.x == 0) {
        float m = red[0];
        #pragma unroll
        for (int w = 1; w < 8; w++) m = fmaxf(m, red[w]);
        atomicMax(&g_Tbits, fkey(m));          // one atomic per block
    }
}

// ==================== Kernel 3: HMMA flash (R8 core + fused finalize) =======
#define LD 72                                   // halves per smem row (144 B)
static constexpr uint32_t BS_BUF = 256 * LD * 2;          // 36864
static constexpr uint32_t AS_OFF = 2 * BS_BUF;            // 73728
static constexpr uint32_t AS_BUF = MT * LD * 2;           // 9216
static constexpr uint32_t EF_OFF = AS_OFF + 2 * AS_BUF;   // 92160
static constexpr uint32_t LS_OFF = EF_OFF + N_NODES * 4;  // 124928
static constexpr uint32_t SMEM_TOTAL = LS_OFF + 256;      // 125184

__global__ void __launch_bounds__(FTH) flash_mma_kernel(
    const int* __restrict__ adj, const float* __restrict__ abp,
    float* __restrict__ out)
{
    extern __shared__ __align__(16) char smem[];
    const uint32_t sbase = smem_u32(smem);
    uint32_t* EFs = (uint32_t*)(smem + EF_OFF);
    float* lsum_s = (float*)(smem + LS_OFF);

    const int tid  = threadIdx.x;
    const int lane = tid & 31;
    const int warp = tid >> 5;
    const int rowbase = blockIdx.x * MT;

    // ---- fused finalize: build EF table in SMEM from g_t (32 KB) ----
    const float T  = finv(g_Tbits);
    const float ab = abp[0];
    #pragma unroll
    for (int i = 0; i < 16; i++) {
        int n = tid + i * FTH;
        float t = g_t[n];
        EFs[n] = packh2(__expf(t - T), __expf(0.2f * (t - T)));
    }

    // ---- per-thread P-gen constants (fused finalize per-row part) ----
    const int prow = tid >> 3;           // 0..63
    const int pseg = tid & 7;            // 8 j's each
    const int row  = rowbase + prow;
    const float u  = g_ssrc[row] + ab + T;
    const float M  = u > 0.f ? u : 0.2f * u;
    const float alpha = __expf(u - M);
    const float beta  = __expf(0.2f * u - M);
    const float thr   = __expf(-u);
    float lpriv = 0.f;

    const int* adjrow = adj + (size_t)row * N_NODES;
    const uint32_t a_st0 = sbase + AS_OFF + (uint32_t)((prow * LD + pseg * 8) * 2);

    // ---- mma addressing: warp grid 2m x 8n ----
    const int mw = warp >> 3;
    const int nw = warp & 7;
    const uint32_t a_lane0 = sbase + AS_OFF +
        (uint32_t)(((mw * 32 + (lane & 15)) * LD + (lane >> 4) * 8) * 2);
    const uint32_t b_lane0 = sbase +
        (uint32_t)(((nw * 32 + (lane & 7) + ((lane >> 4) << 3)) * LD
                    + ((lane >> 3) & 1) * 8) * 2);

    float acc[2][4][4];
    #pragma unroll
    for (int mi = 0; mi < 2; mi++)
        #pragma unroll
        for (int nt = 0; nt < 4; nt++)
            #pragma unroll
            for (int u2 = 0; u2 < 4; u2++) acc[mi][nt][u2] = 0.f;

    auto stageB = [&](int kc, int buf) {
        const int k0 = kc * KC;
        const uint32_t bb = sbase + (uint32_t)buf * BS_BUF;
        #pragma unroll
        for (int i = 0; i < 4; i++) {
            int f = tid + i * FTH;
            int n = f >> 3;
            int c = (f & 7) * 8;
            cp16(bb + (uint32_t)((n * LD + c) * 2),
                 g_whT + (size_t)n * N_NODES + k0 + c);
        }
    };

    // ---- P-gen from prefetched adj regs + half2 EF table ----
    auto pgen = [&](int kc, int buf, int4 q0, int4 q1) {
        const int jb = kc * KC + pseg * 8;
        uint4 u0 = *(const uint4*)(EFs + jb);
        uint4 u1 = *(const uint4*)(EFs + jb + 4);
        float2 ef;
        ef = unph2(u0.x); float p0 = q0.x > 0 ? (ef.x > thr ? alpha * ef.x : beta * ef.y) : 0.f;
        ef = unph2(u0.y); float p1 = q0.y > 0 ? (ef.x > thr ? alpha * ef.x : beta * ef.y) : 0.f;
        ef = unph2(u0.z); float p2 = q0.z > 0 ? (ef.x > thr ? alpha * ef.x : beta * ef.y) : 0.f;
        ef = unph2(u0.w); float p3 = q0.w > 0 ? (ef.x > thr ? alpha * ef.x : beta * ef.y) : 0.f;
        ef = unph2(u1.x); float p4 = q1.x > 0 ? (ef.x > thr ? alpha * ef.x : beta * ef.y) : 0.f;
        ef = unph2(u1.y); float p5 = q1.y > 0 ? (ef.x > thr ? alpha * ef.x : beta * ef.y) : 0.f;
        ef = unph2(u1.z); float p6 = q1.z > 0 ? (ef.x > thr ? alpha * ef.x : beta * ef.y) : 0.f;
        ef = unph2(u1.w); float p7 = q1.w > 0 ? (ef.x > thr ? alpha * ef.x : beta * ef.y) : 0.f;
        lpriv += ((p0 + p1) + (p2 + p3)) + ((p4 + p5) + (p6 + p7));
        uint4 w;
        w.x = packh2(p0, p1); w.y = packh2(p2, p3);
        w.z = packh2(p4, p5); w.w = packh2(p6, p7);
        uint32_t dst = a_st0 + (uint32_t)buf * AS_BUF;
        asm volatile("st.shared.v4.b32 [%0], {%1,%2,%3,%4};"
                     :: "r"(dst), "r"(w.x), "r"(w.y), "r"(w.z), "r"(w.w) : "memory");
    };

    // fragment loader for one ks step
    auto ld_frags = [&](uint32_t a_lane, uint32_t b_lane, int ks,
                        uint32_t (*af)[4], uint32_t (*bf)[4]) {
        ldmatrix_x4(bf[0][0], bf[0][1], bf[0][2], bf[0][3],
                    b_lane + (uint32_t)(ks * 32));
        ldmatrix_x4(bf[1][0], bf[1][1], bf[1][2], bf[1][3],
                    b_lane + (uint32_t)(16 * LD * 2 + ks * 32));
        ldmatrix_x4(af[0][0], af[0][1], af[0][2], af[0][3],
                    a_lane + (uint32_t)(ks * 32));
        ldmatrix_x4(af[1][0], af[1][1], af[1][2], af[1][3],
                    a_lane + (uint32_t)(16 * LD * 2 + ks * 32));
    };

    // ---- prologue ----
    stageB(0, 0);
    CP_COMMIT();
    __syncthreads();          // EFs visible
    {
        const int4* ap = (const int4*)(adjrow) + pseg * 2;
        int4 q0 = ap[0], q1 = ap[1];
        pgen(0, 0, q0, q1);
    }
    CP_WAIT0();
    __syncthreads();          // Bs[0], As[0] ready

    // ---- main loop: one sync per chunk, reg-pipelined fragments ----
    #pragma unroll 2
    for (int kt = 0; kt < NCH; kt++) {
        const int buf = kt & 1;
        int4 qn0, qn1;
        if (kt + 1 < NCH) {
            stageB(kt + 1, buf ^ 1);
            CP_COMMIT();
            const int4* ap = (const int4*)(adjrow + (kt + 1) * KC) + pseg * 2;
            qn0 = ap[0]; qn1 = ap[1];      // prefetch adj for next chunk
        }

        const uint32_t a_lane = a_lane0 + (uint32_t)buf * AS_BUF;
        const uint32_t b_lane = b_lane0 + (uint32_t)buf * BS_BUF;

        uint32_t af[2][2][4], bf[2][2][4];
        ld_frags(a_lane, b_lane, 0, af[0], bf[0]);
        #pragma unroll
        for (int ks = 0; ks < 4; ks++) {
            const int par = ks & 1;
            if (ks < 3) ld_frags(a_lane, b_lane, ks + 1, af[par ^ 1], bf[par ^ 1]);
            #pragma unroll
            for (int mi = 0; mi < 2; mi++) {
                mma16816(acc[mi][0], af[par][mi][0], af[par][mi][1],
                         af[par][mi][2], af[par][mi][3], bf[par][0][0], bf[par][0][1]);
                mma16816(acc[mi][1], af[par][mi][0], af[par][mi][1],
                         af[par][mi][2], af[par][mi][3], bf[par][0][2], bf[par][0][3]);
                mma16816(acc[mi][2], af[par][mi][0], af[par][mi][1],
                         af[par][mi][2], af[par][mi][3], bf[par][1][0], bf[par][1][1]);
                mma16816(acc[mi][3], af[par][mi][0], af[par][mi][1],
                         af[par][mi][2], af[par][mi][3], bf[par][1][2], bf[par][1][3]);
            }
        }
        if (kt + 1 < NCH) pgen(kt + 1, buf ^ 1, qn0, qn1);
        CP_WAIT0();
        __syncthreads();
    }

    // ---- lsum ----
    lpriv += __shfl_xor_sync(0xffffffffu, lpriv, 1);
    lpriv += __shfl_xor_sync(0xffffffffu, lpriv, 2);
    lpriv += __shfl_xor_sync(0xffffffffu, lpriv, 4);
    if ((lane & 7) == 0) lsum_s[prow] = lpriv;
    __syncthreads();

    // ---- write out ----
    #pragma unroll
    for (int mi = 0; mi < 2; mi++) {
        int r0 = mw * 32 + mi * 16 + (lane >> 2);
        int r1 = r0 + 8;
        float inv0 = 1.f / lsum_s[r0];
        float inv1 = 1.f / lsum_s[r1];
        #pragma unroll
        for (int nt = 0; nt < 4; nt++) {
            int c = nw * 32 + nt * 8 + ((lane & 3) << 1);
            float2 v0 = make_float2(acc[mi][nt][0] * inv0, acc[mi][nt][1] * inv0);
            float2 v1 = make_float2(acc[mi][nt][2] * inv1, acc[mi][nt][3] * inv1);
            *(float2*)&out[(size_t)(rowbase + r0) * D_OUT + c] = v0;
            *(float2*)&out[(size_t)(rowbase + r1) * D_OUT + c] = v1;
        }
    }
}

// ==================== launch ================================================
extern "C" void kernel_launch(void* const* d_in, const int* in_sizes, int n_in,
                              void* d_out, int out_size)
{
    const float* h   = (const float*)d_in[0];
    const int*   adj = (const int*)  d_in[1];
    const float* Ww  = (const float*)d_in[2];
    const float* Wb  = (const float*)d_in[3];
    const float* aw  = (const float*)d_in[4];
    const float* ab  = (const float*)d_in[5];
    float* out = (float*)d_out;

    cudaFuncSetAttribute(gemm_wh_kernel,
                         cudaFuncAttributeMaxDynamicSharedMemorySize, GEMM_SMEM);
    cudaFuncSetAttribute(flash_mma_kernel,
                         cudaFuncAttributeMaxDynamicSharedMemorySize, SMEM_TOTAL);

    gemm_wh_kernel<<<dim3(D_OUT / 128, N_NODES / 128), 512, GEMM_SMEM>>>(h, Ww, Wb);
    scores_kernel<<<N_NODES / 8, 256>>>(aw);
    flash_mma_kernel<<<N_NODES / MT, FTH, SMEM_TOTAL>>>(adj, ab, out);
}

// round 17
// speedup vs baseline: 1.4146x; 1.0504x over previous
#include <cuda_runtime.h>
#include <cuda_fp16.h>
#include <cstdint>

#define N_NODES 8192
#define D_IN    512
#define D_OUT   256
#define KC      64
#define NCH     (N_NODES / KC)
#define MT      64
#define FTH     512

// ---------------- scratch (device globals) ----------------------------------
static __device__ float    g_wh [N_NODES * D_OUT];   // fp32 wh (8 MB)
static __device__ __half   g_whT[D_OUT * N_NODES];   // fp16 wh^T (4 MB)
static __device__ float    g_ssrc[N_NODES];
static __device__ float    g_t[N_NODES];
static __device__ unsigned g_Tbits;

// ---------------- PTX helpers -----------------------------------------------
__device__ __forceinline__ uint32_t smem_u32(const void* p) {
    uint32_t a;
    asm("{ .reg .u64 t; cvta.to.shared.u64 t, %1; cvt.u32.u64 %0, t; }"
        : "=r"(a) : "l"(p));
    return a;
}
__device__ __forceinline__ void ldmatrix_x4(uint32_t& r0, uint32_t& r1,
                                            uint32_t& r2, uint32_t& r3,
                                            uint32_t addr) {
    asm volatile("ldmatrix.sync.aligned.m8n8.x4.shared.b16 {%0,%1,%2,%3}, [%4];"
                 : "=r"(r0), "=r"(r1), "=r"(r2), "=r"(r3) : "r"(addr));
}
__device__ __forceinline__ void mma16816(float* c,
                                         uint32_t a0, uint32_t a1, uint32_t a2, uint32_t a3,
                                         uint32_t b0, uint32_t b1) {
    asm volatile("mma.sync.aligned.m16n8k16.row.col.f32.f16.f16.f32 "
                 "{%0,%1,%2,%3}, {%4,%5,%6,%7}, {%8,%9}, {%0,%1,%2,%3};"
                 : "+f"(c[0]), "+f"(c[1]), "+f"(c[2]), "+f"(c[3])
                 : "r"(a0), "r"(a1), "r"(a2), "r"(a3), "r"(b0), "r"(b1));
}
__device__ __forceinline__ void cp16(uint32_t dst, const void* src) {
    asm volatile("cp.async.ca.shared.global [%0], [%1], 16;"
                 :: "r"(dst), "l"(src) : "memory");
}
#define CP_COMMIT() asm volatile("cp.async.commit_group;" ::: "memory")
#define CP_WAIT0()  asm volatile("cp.async.wait_group 0;" ::: "memory")

__device__ __forceinline__ unsigned fkey(float x) {
    int i = __float_as_int(x);
    return i >= 0 ? ((unsigned)i | 0x80000000u) : ~(unsigned)i;
}
__device__ __forceinline__ float finv(unsigned k) {
    return (k & 0x80000000u) ? __int_as_float((int)(k & 0x7fffffffu))
                             : __int_as_float((int)~k);
}
__device__ __forceinline__ uint32_t packh2(float a, float b) {
    __half2 h = __floats2half2_rn(a, b);
    return *(uint32_t*)&h;
}
__device__ __forceinline__ float2 unph2(uint32_t u) {
    return __half22float2(*(__half2*)&u);
}

// ==================== Kernel 1: wh = h @ W^T + b  (HMMA fp16, reg-pipelined)
#define GLD 72
static constexpr uint32_t GA_BUF = 128 * GLD * 2;
static constexpr uint32_t GB_OFF = 2 * GA_BUF;
static constexpr uint32_t GEMM_SMEM = 4 * GA_BUF;
#define LDT 136

__global__ void __launch_bounds__(512) gemm_wh_kernel(
    const float* __restrict__ h, const float* __restrict__ W,
    const float* __restrict__ Wb)
{
    extern __shared__ __align__(16) char smem[];
    const uint32_t sbase = smem_u32(smem);
    const int tid  = threadIdx.x;
    const int lane = tid & 31;
    const int warp = tid >> 5;
    const int mw = warp >> 2;
    const int nw = warp & 3;
    const int row0 = blockIdx.y * 128;
    const int col0 = blockIdx.x * 128;

    if (blockIdx.x == 0 && blockIdx.y == 0 && tid == 0) g_Tbits = 0u;

    // per-thread staging coords (4 items of 4 floats each)
    int srow[4], scol[4];
    #pragma unroll
    for (int i = 0; i < 4; i++) {
        int f = tid + i * 512;
        srow[i] = f >> 4;
        scol[i] = (f & 15) << 2;
    }

    // LDG prefetch of chunk (fp32) into regs
    float4 rh[4], rw[4];
    auto ldchunk = [&](int kb) {
        #pragma unroll
        for (int i = 0; i < 4; i++) {
            rh[i] = *(const float4*)&h[(size_t)(row0 + srow[i]) * D_IN + kb + scol[i]];
            rw[i] = *(const float4*)&W[(size_t)(col0 + srow[i]) * D_IN + kb + scol[i]];
        }
    };
    // convert + STS into buffer
    auto stchunk = [&](int buf) {
        __half* Ah = (__half*)(smem + buf * GA_BUF);
        __half* Bh = (__half*)(smem + GB_OFF + buf * GA_BUF);
        #pragma unroll
        for (int i = 0; i < 4; i++) {
            *(uint2*)(Ah + srow[i] * GLD + scol[i]) =
                make_uint2(packh2(rh[i].x, rh[i].y), packh2(rh[i].z, rh[i].w));
            *(uint2*)(Bh + srow[i] * GLD + scol[i]) =
                make_uint2(packh2(rw[i].x, rw[i].y), packh2(rw[i].z, rw[i].w));
        }
    };

    const uint32_t a_lane0 = sbase +
        (uint32_t)(((mw * 32 + (lane & 15)) * GLD + (lane >> 4) * 8) * 2);
    const uint32_t b_lane0 = sbase + GB_OFF +
        (uint32_t)(((nw * 32 + (lane & 7) + ((lane >> 4) << 3)) * GLD
                    + ((lane >> 3) & 1) * 8) * 2);

    float acc[2][4][4];
    #pragma unroll
    for (int mi = 0; mi < 2; mi++)
        #pragma unroll
        for (int nt = 0; nt < 4; nt++)
            #pragma unroll
            for (int u = 0; u < 4; u++) acc[mi][nt][u] = 0.f;

    ldchunk(0);
    stchunk(0);
    __syncthreads();

    #pragma unroll 1
    for (int kt = 0; kt < 8; kt++) {
        const int buf = kt & 1;
        if (kt < 7) ldchunk((kt + 1) * 64);    // LDG issued before mma block
        const uint32_t a_lane = a_lane0 + (uint32_t)buf * GA_BUF;
        const uint32_t b_lane = b_lane0 + (uint32_t)buf * GA_BUF;
        #pragma unroll
        for (int ks = 0; ks < 4; ks++) {
            uint32_t b[2][4];
            ldmatrix_x4(b[0][0], b[0][1], b[0][2], b[0][3], b_lane + ks * 32);
            ldmatrix_x4(b[1][0], b[1][1], b[1][2], b[1][3],
                        b_lane + 16 * GLD * 2 + ks * 32);
            #pragma unroll
            for (int mi = 0; mi < 2; mi++) {
                uint32_t a0, a1, a2, a3;
                ldmatrix_x4(a0, a1, a2, a3, a_lane + mi * 16 * GLD * 2 + ks * 32);
                mma16816(acc[mi][0], a0, a1, a2, a3, b[0][0], b[0][1]);
                mma16816(acc[mi][1], a0, a1, a2, a3, b[0][2], b[0][3]);
                mma16816(acc[mi][2], a0, a1, a2, a3, b[1][0], b[1][1]);
                mma16816(acc[mi][3], a0, a1, a2, a3, b[1][2], b[1][3]);
            }
        }
        if (kt < 7) stchunk(buf ^ 1);          // convert + STS after mma
        __syncthreads();
    }

    __half* tT = (__half*)smem;
    #pragma unroll
    for (int nt = 0; nt < 4; nt++) {
        int cl = nw * 32 + nt * 8 + ((lane & 3) << 1);
        float2 bb = *(const float2*)&Wb[col0 + cl];
        #pragma unroll
        for (int mi = 0; mi < 2; mi++) {
            int rl0 = mw * 32 + mi * 16 + (lane >> 2);
            int rl1 = rl0 + 8;
            float v00 = acc[mi][nt][0] + bb.x;
            float v01 = acc[mi][nt][1] + bb.y;
            float v10 = acc[mi][nt][2] + bb.x;
            float v11 = acc[mi][nt][3] + bb.y;
            *(float2*)&g_wh[(size_t)(row0 + rl0) * D_OUT + col0 + cl] = make_float2(v00, v01);
            *(float2*)&g_wh[(size_t)(row0 + rl1) * D_OUT + col0 + cl] = make_float2(v10, v11);
            tT[cl * LDT + rl0]       = __float2half(v00);
            tT[(cl + 1) * LDT + rl0] = __float2half(v01);
            tT[cl * LDT + rl1]       = __float2half(v10);
            tT[(cl + 1) * LDT + rl1] = __float2half(v11);
        }
    }
    __syncthreads();
    {
        int c = tid >> 2;
        int seg = (tid & 3) << 5;
        const uint4* src = (const uint4*)(tT + c * LDT + seg);
        uint4* dst = (uint4*)(g_whT + (size_t)(col0 + c) * N_NODES + row0 + seg);
        #pragma unroll
        for (int i = 0; i < 4; i++) dst[i] = src[i];
    }
}

// ==================== Kernel 2: per-row scores (+ global max of t) ==========
__global__ void __launch_bounds__(256) scores_kernel(const float* __restrict__ aw)
{
    __shared__ float red[8];
    const int lane = threadIdx.x & 31;
    const int warp = threadIdx.x >> 5;
    const int row  = blockIdx.x * 8 + warp;

    const float4* whr = (const float4*)&g_wh[(size_t)row * D_OUT];
    float4 w0 = whr[lane * 2];
    float4 w1 = whr[lane * 2 + 1];
    const float4* as = (const float4*)aw;
    const float4* ad = (const float4*)(aw + D_OUT);
    float4 a0 = as[lane * 2], a1 = as[lane * 2 + 1];
    float4 b0 = ad[lane * 2], b1 = ad[lane * 2 + 1];

    float ss = w0.x*a0.x + w0.y*a0.y + w0.z*a0.z + w0.w*a0.w
             + w1.x*a1.x + w1.y*a1.y + w1.z*a1.z + w1.w*a1.w;
    float sd = w0.x*b0.x + w0.y*b0.y + w0.z*b0.z + w0.w*b0.w
             + w1.x*b1.x + w1.y*b1.y + w1.z*b1.z + w1.w*b1.w;
    #pragma unroll
    for (int o = 16; o; o >>= 1) {
        ss += __shfl_xor_sync(0xffffffffu, ss, o);
        sd += __shfl_xor_sync(0xffffffffu, sd, o);
    }
    if (lane == 0) {
        g_ssrc[row] = ss;
        g_t[row]    = sd;
        red[warp]   = sd;
    }
    __syncthreads();
    if (threadIdx.x == 0) {
        float m = red[0];
        #pragma unroll
        for (int w = 1; w < 8; w++) m = fmaxf(m, red[w]);
        atomicMax(&g_Tbits, fkey(m));          // one atomic per block
    }
}

// ==================== Kernel 3: HMMA flash (R8 core + fused finalize) =======
#define LD 72                                   // halves per smem row (144 B)
static constexpr uint32_t BS_BUF = 256 * LD * 2;          // 36864
static constexpr uint32_t AS_OFF = 2 * BS_BUF;            // 73728
static constexpr uint32_t AS_BUF = MT * LD * 2;           // 9216
static constexpr uint32_t EF_OFF = AS_OFF + 2 * AS_BUF;   // 92160
static constexpr uint32_t LS_OFF = EF_OFF + N_NODES * 4;  // 124928
static constexpr uint32_t SMEM_TOTAL = LS_OFF + 256;      // 125184

__global__ void __launch_bounds__(FTH) flash_mma_kernel(
    const int* __restrict__ adj, const float* __restrict__ abp,
    float* __restrict__ out)
{
    extern __shared__ __align__(16) char smem[];
    const uint32_t sbase = smem_u32(smem);
    uint32_t* EFs = (uint32_t*)(smem + EF_OFF);
    float* lsum_s = (float*)(smem + LS_OFF);

    const int tid  = threadIdx.x;
    const int lane = tid & 31;
    const int warp = tid >> 5;
    const int rowbase = blockIdx.x * MT;

    // ---- fused finalize: build EF table in SMEM from g_t (32 KB) ----
    const float T  = finv(g_Tbits);
    const float ab = abp[0];
    #pragma unroll
    for (int i = 0; i < 16; i++) {
        int n = tid + i * FTH;
        float t = g_t[n];
        EFs[n] = packh2(__expf(t - T), __expf(0.2f * (t - T)));
    }

    // ---- per-thread P-gen constants (fused finalize per-row part) ----
    const int prow = tid >> 3;           // 0..63
    const int pseg = tid & 7;            // 8 j's each
    const int row  = rowbase + prow;
    const float u  = g_ssrc[row] + ab + T;
    const float M  = u > 0.f ? u : 0.2f * u;
    const float alpha = __expf(u - M);
    const float beta  = __expf(0.2f * u - M);
    const float thr   = __expf(-u);
    float lpriv = 0.f;

    const int* adjrow = adj + (size_t)row * N_NODES;
    const uint32_t a_st0 = sbase + AS_OFF + (uint32_t)((prow * LD + pseg * 8) * 2);

    // ---- mma addressing: warp grid 2m x 8n ----
    const int mw = warp >> 3;
    const int nw = warp & 7;
    const uint32_t a_lane0 = sbase + AS_OFF +
        (uint32_t)(((mw * 32 + (lane & 15)) * LD + (lane >> 4) * 8) * 2);
    const uint32_t b_lane0 = sbase +
        (uint32_t)(((nw * 32 + (lane & 7) + ((lane >> 4) << 3)) * LD
                    + ((lane >> 3) & 1) * 8) * 2);

    float acc[2][4][4];
    #pragma unroll
    for (int mi = 0; mi < 2; mi++)
        #pragma unroll
        for (int nt = 0; nt < 4; nt++)
            #pragma unroll
            for (int u2 = 0; u2 < 4; u2++) acc[mi][nt][u2] = 0.f;

    auto stageB = [&](int kc, int buf) {
        const int k0 = kc * KC;
        const uint32_t bb = sbase + (uint32_t)buf * BS_BUF;
        #pragma unroll
        for (int i = 0; i < 4; i++) {
            int f = tid + i * FTH;
            int n = f >> 3;
            int c = (f & 7) * 8;
            cp16(bb + (uint32_t)((n * LD + c) * 2),
                 g_whT + (size_t)n * N_NODES + k0 + c);
        }
    };

    // ---- P-gen from prefetched adj regs + half2 EF table ----
    auto pgen = [&](int kc, int buf, int4 q0, int4 q1) {
        const int jb = kc * KC + pseg * 8;
        uint4 u0 = *(const uint4*)(EFs + jb);
        uint4 u1 = *(const uint4*)(EFs + jb + 4);
        float2 ef;
        ef = unph2(u0.x); float p0 = q0.x > 0 ? (ef.x > thr ? alpha * ef.x : beta * ef.y) : 0.f;
        ef = unph2(u0.y); float p1 = q0.y > 0 ? (ef.x > thr ? alpha * ef.x : beta * ef.y) : 0.f;
        ef = unph2(u0.z); float p2 = q0.z > 0 ? (ef.x > thr ? alpha * ef.x : beta * ef.y) : 0.f;
        ef = unph2(u0.w); float p3 = q0.w > 0 ? (ef.x > thr ? alpha * ef.x : beta * ef.y) : 0.f;
        ef = unph2(u1.x); float p4 = q1.x > 0 ? (ef.x > thr ? alpha * ef.x : beta * ef.y) : 0.f;
        ef = unph2(u1.y); float p5 = q1.y > 0 ? (ef.x > thr ? alpha * ef.x : beta * ef.y) : 0.f;
        ef = unph2(u1.z); float p6 = q1.z > 0 ? (ef.x > thr ? alpha * ef.x : beta * ef.y) : 0.f;
        ef = unph2(u1.w); float p7 = q1.w > 0 ? (ef.x > thr ? alpha * ef.x : beta * ef.y) : 0.f;
        lpriv += ((p0 + p1) + (p2 + p3)) + ((p4 + p5) + (p6 + p7));
        uint4 w;
        w.x = packh2(p0, p1); w.y = packh2(p2, p3);
        w.z = packh2(p4, p5); w.w = packh2(p6, p7);
        uint32_t dst = a_st0 + (uint32_t)buf * AS_BUF;
        asm volatile("st.shared.v4.b32 [%0], {%1,%2,%3,%4};"
                     :: "r"(dst), "r"(w.x), "r"(w.y), "r"(w.z), "r"(w.w) : "memory");
    };

    // fragment loader for one ks step
    auto ld_frags = [&](uint32_t a_lane, uint32_t b_lane, int ks,
                        uint32_t (*af)[4], uint32_t (*bf)[4]) {
        ldmatrix_x4(bf[0][0], bf[0][1], bf[0][2], bf[0][3],
                    b_lane + (uint32_t)(ks * 32));
        ldmatrix_x4(bf[1][0], bf[1][1], bf[1][2], bf[1][3],
                    b_lane + (uint32_t)(16 * LD * 2 + ks * 32));
        ldmatrix_x4(af[0][0], af[0][1], af[0][2], af[0][3],
                    a_lane + (uint32_t)(ks * 32));
        ldmatrix_x4(af[1][0], af[1][1], af[1][2], af[1][3],
                    a_lane + (uint32_t)(16 * LD * 2 + ks * 32));
    };

    // ---- prologue ----
    stageB(0, 0);
    CP_COMMIT();
    __syncthreads();          // EFs visible
    {
        const int4* ap = (const int4*)(adjrow) + pseg * 2;
        int4 q0 = ap[0], q1 = ap[1];
        pgen(0, 0, q0, q1);
    }
    CP_WAIT0();
    __syncthreads();          // Bs[0], As[0] ready

    // ---- main loop: one sync per chunk, reg-pipelined fragments ----
    #pragma unroll 2
    for (int kt = 0; kt < NCH; kt++) {
        const int buf = kt & 1;
        int4 qn0, qn1;
        if (kt + 1 < NCH) {
            stageB(kt + 1, buf ^ 1);
            CP_COMMIT();
            const int4* ap = (const int4*)(adjrow + (kt + 1) * KC) + pseg * 2;
            qn0 = ap[0]; qn1 = ap[1];      // prefetch adj for next chunk
        }

        const uint32_t a_lane = a_lane0 + (uint32_t)buf * AS_BUF;
        const uint32_t b_lane = b_lane0 + (uint32_t)buf * BS_BUF;

        uint32_t af[2][2][4], bf[2][2][4];
        ld_frags(a_lane, b_lane, 0, af[0], bf[0]);
        #pragma unroll
        for (int ks = 0; ks < 4; ks++) {
            const int par = ks & 1;
            if (ks < 3) ld_frags(a_lane, b_lane, ks + 1, af[par ^ 1], bf[par ^ 1]);
            #pragma unroll
            for (int mi = 0; mi < 2; mi++) {
                mma16816(acc[mi][0], af[par][mi][0], af[par][mi][1],
                         af[par][mi][2], af[par][mi][3], bf[par][0][0], bf[par][0][1]);
                mma16816(acc[mi][1], af[par][mi][0], af[par][mi][1],
                         af[par][mi][2], af[par][mi][3], bf[par][0][2], bf[par][0][3]);
                mma16816(acc[mi][2], af[par][mi][0], af[par][mi][1],
                         af[par][mi][2], af[par][mi][3], bf[par][1][0], bf[par][1][1]);
                mma16816(acc[mi][3], af[par][mi][0], af[par][mi][1],
                         af[par][mi][2], af[par][mi][3], bf[par][1][2], bf[par][1][3]);
            }
        }
        if (kt + 1 < NCH) pgen(kt + 1, buf ^ 1, qn0, qn1);
        CP_WAIT0();
        __syncthreads();
    }

    // ---- lsum ----
    lpriv += __shfl_xor_sync(0xffffffffu, lpriv, 1);
    lpriv += __shfl_xor_sync(0xffffffffu, lpriv, 2);
    lpriv += __shfl_xor_sync(0xffffffffu, lpriv, 4);
    if ((lane & 7) == 0) lsum_s[prow] = lpriv;
    __syncthreads();

    // ---- write out ----
    #pragma unroll
    for (int mi = 0; mi < 2; mi++) {
        int r0 = mw * 32 + mi * 16 + (lane >> 2);
        int r1 = r0 + 8;
        float inv0 = 1.f / lsum_s[r0];
        float inv1 = 1.f / lsum_s[r1];
        #pragma unroll
        for (int nt = 0; nt < 4; nt++) {
            int c = nw * 32 + nt * 8 + ((lane & 3) << 1);
            float2 v0 = make_float2(acc[mi][nt][0] * inv0, acc[mi][nt][1] * inv0);
            float2 v1 = make_float2(acc[mi][nt][2] * inv1, acc[mi][nt][3] * inv1);
            *(float2*)&out[(size_t)(rowbase + r0) * D_OUT + c] = v0;
            *(float2*)&out[(size_t)(rowbase + r1) * D_OUT + c] = v1;
        }
    }
}

// ==================== launch ================================================
extern "C" void kernel_launch(void* const* d_in, const int* in_sizes, int n_in,
                              void* d_out, int out_size)
{
    const float* h   = (const float*)d_in[0];
    const int*   adj = (const int*)  d_in[1];
    const float* Ww  = (const float*)d_in[2];
    const float* Wb  = (const float*)d_in[3];
    const float* aw  = (const float*)d_in[4];
    const float* ab  = (const float*)d_in[5];
    float* out = (float*)d_out;

    cudaFuncSetAttribute(gemm_wh_kernel,
                         cudaFuncAttributeMaxDynamicSharedMemorySize, GEMM_SMEM);
    cudaFuncSetAttribute(flash_mma_kernel,
                         cudaFuncAttributeMaxDynamicSharedMemorySize, SMEM_TOTAL);

    gemm_wh_kernel<<<dim3(D_OUT / 128, N_NODES / 128), 512, GEMM_SMEM>>>(h, Ww, Wb);
    scores_kernel<<<N_NODES / 8, 256>>>(aw);
    flash_mma_kernel<<<N_NODES / MT, FTH, SMEM_TOTAL>>>(adj, ab, out);
}